// round 16
// baseline (speedup 1.0000x reference)
#include <cuda_runtime.h>
#include <cuda_bf16.h>
#include <math.h>
#include <stdint.h>

// ---------------------------------------------------------------------------
// Problem constants
// ---------------------------------------------------------------------------
#define NTOK   4096      // B*S
#define DDIM   256
#define DLF    768
#define ADIM   128
#define DSUM   1536
#define HIDD   64

typedef unsigned long long ull;

// ---------------------------------------------------------------------------
// helpers
// ---------------------------------------------------------------------------
__device__ __forceinline__ float gelu_f(float v) {
    return 0.5f * v * (1.0f + erff(v * 0.70710678118654752440f));
}
__device__ __forceinline__ uint32_t smem_to_u32(const void* p) {
    uint32_t a;
    asm("{ .reg .u64 t; cvta.to.shared.u64 t, %1; cvt.u32.u64 %0, t; }" : "=r"(a) : "l"(p));
    return a;
}
#define SMEM_SWIZZLE_128B(o) ((o) ^ (((o) >> 3) & 0x70))

__device__ __forceinline__ void cp_async16(uint32_t saddr, const void* gptr) {
    asm volatile("cp.async.cg.shared.global [%0], [%1], 16;" :: "r"(saddr), "l"(gptr));
}
#define CP_COMMIT() asm volatile("cp.async.commit_group;" ::: "memory")
#define CP_WAIT1()  asm volatile("cp.async.wait_group 1;"  ::: "memory")
#define CP_WAIT0()  asm volatile("cp.async.wait_group 0;"  ::: "memory")

__device__ __forceinline__ void ldsm_x4(uint32_t addr, uint32_t& r0, uint32_t& r1,
                                        uint32_t& r2, uint32_t& r3) {
    asm volatile("ldmatrix.sync.aligned.m8n8.x4.shared.b16 {%0,%1,%2,%3}, [%4];"
                 : "=r"(r0), "=r"(r1), "=r"(r2), "=r"(r3) : "r"(addr));
}
__device__ __forceinline__ void ldsm_x2(uint32_t addr, uint32_t& r0, uint32_t& r1) {
    asm volatile("ldmatrix.sync.aligned.m8n8.x2.shared.b16 {%0,%1}, [%2];"
                 : "=r"(r0), "=r"(r1) : "r"(addr));
}
__device__ __forceinline__ void mma16816(float& c0, float& c1, float& c2, float& c3,
                                         uint32_t a0, uint32_t a1, uint32_t a2, uint32_t a3,
                                         uint32_t b0, uint32_t b1) {
    asm volatile("mma.sync.aligned.m16n8k16.row.col.f32.bf16.bf16.f32 "
                 "{%0,%1,%2,%3}, {%4,%5,%6,%7}, {%8,%9}, {%0,%1,%2,%3};"
                 : "+f"(c0), "+f"(c1), "+f"(c2), "+f"(c3)
                 : "r"(a0), "r"(a1), "r"(a2), "r"(a3), "r"(b0), "r"(b1));
}

__device__ __forceinline__ void split_store(float v, __nv_bfloat16* hi, __nv_bfloat16* lo) {
    __nv_bfloat16 h = __float2bfloat16(v);
    *hi = h;
    *lo = __float2bfloat16(v - __bfloat162float(h));
}

// ---------------------------------------------------------------------------
// Scratch (fp32 region then bf16 region)
// ---------------------------------------------------------------------------
#define OFF_ADAPT   0u
#define OFF_AM      524288u
#define OFF_PART    524416u
#define OFF_GATE    528512u
#define OFF_WDYN    548992u
#define OFF_BCAT    942208u
#define OFF_MIX     943744u
#define OFF_KA      7497344u
#define OFF_RESID   14837376u
#define OFF_H       21128832u
#define OFF_KAPART  27682432u          // 4 slices x 4096 x 64
#define OFF_BF16    28731008u          // start of bf16 region (float units)

// bf16 offsets (in bf16 elements from bf16 base)
#define BF_XH    0u
#define BF_XL    1048576u
#define BF_WFH   2097152u
#define BF_WFL   2129920u
#define BF_WDH   2162688u
#define BF_WDL   2555904u
#define BF_TPH   2949120u
#define BF_TPL   3211264u
#define BF_WPH   3473408u
#define BF_WPL   3489792u
#define BF_CATH  3506176u
#define BF_CATL  9797632u
#define BF_WRH   16089088u
#define BF_WRL   18448384u
#define BF_W1H   20807680u
#define BF_W1L   20905984u
#define BF_CBH   21004288u
#define BF_CBL   27295744u
#define BF_WOH   33587200u
#define BF_WOL   33980416u
#define BF_WP1H  34373632u             // Wpsi1^T hi [64][16384]
#define BF_WP1L  35422208u

#define SCRATCH_FLOATS (28731008u + 18235392u)
__device__ float g_scratch[SCRATCH_FLOATS];

// ---------------------------------------------------------------------------
// split: fp32 [n] -> bf16 hi, lo
// ---------------------------------------------------------------------------
__global__ void split_kernel(const float* __restrict__ src,
                             __nv_bfloat16* __restrict__ hi,
                             __nv_bfloat16* __restrict__ lo)
{
    const int i = blockIdx.x * 256 + threadIdx.x;
    float4 v = ((const float4*)src)[i];
    __nv_bfloat16 hx = __float2bfloat16(v.x), hy = __float2bfloat16(v.y);
    __nv_bfloat16 hz = __float2bfloat16(v.z), hw = __float2bfloat16(v.w);
    __nv_bfloat162* hp = (__nv_bfloat162*)hi;
    __nv_bfloat162* lp = (__nv_bfloat162*)lo;
    hp[2*i]   = __nv_bfloat162(hx, hy);
    hp[2*i+1] = __nv_bfloat162(hz, hw);
    lp[2*i]   = __nv_bfloat162(__float2bfloat16(v.x - __bfloat162float(hx)),
                               __float2bfloat16(v.y - __bfloat162float(hy)));
    lp[2*i+1] = __nv_bfloat162(__float2bfloat16(v.z - __bfloat162float(hz)),
                               __float2bfloat16(v.w - __bfloat162float(hw)));
}

// ---------------------------------------------------------------------------
// transpose+split body (flat 256 threads): W [K,N] fp32 -> th, tl [N,K] bf16
// ---------------------------------------------------------------------------
__device__ __forceinline__ void
tsplit_body(const float* __restrict__ W, __nv_bfloat16* __restrict__ th,
            __nv_bfloat16* __restrict__ tl, int K, int N, int bid)
{
    __shared__ float t[32][33];
    const int nb = (bid % (N / 32)) * 32;
    const int kb = (bid / (N / 32)) * 32;
    const int tx = threadIdx.x & 31, ty = threadIdx.x >> 5;
#pragma unroll
    for (int j = 0; j < 32; j += 8)
        t[ty + j][tx] = W[(size_t)(kb + ty + j) * N + nb + tx];
    __syncthreads();
#pragma unroll
    for (int j = 0; j < 32; j += 8) {
        float v = t[tx][ty + j];
        __nv_bfloat16 h = __float2bfloat16(v);
        th[(size_t)(nb + ty + j) * K + kb + tx] = h;
        tl[(size_t)(nb + ty + j) * K + kb + tx] = __float2bfloat16(v - __bfloat162float(h));
    }
}

__global__ void tsplit_kernel(const float* __restrict__ W,
                              __nv_bfloat16* __restrict__ th,
                              __nv_bfloat16* __restrict__ tl,
                              int K, int N)
{
    tsplit_body(W, th, tl, K, N, blockIdx.x);
}

// prep2: Wfeat tsplit (32) + Wpsi2 tsplit (16) + bcat (6) + lf split (3072)
__global__ void prep2_kernel(const float* __restrict__ W_feat,
                             __nv_bfloat16* __restrict__ wfh, __nv_bfloat16* __restrict__ wfl,
                             const float* __restrict__ Wpsi2,
                             __nv_bfloat16* __restrict__ wph, __nv_bfloat16* __restrict__ wpl,
                             const float* __restrict__ bt, const float* __restrict__ bc,
                             const float* __restrict__ be, float* __restrict__ bcat,
                             const float* __restrict__ lf,
                             __nv_bfloat16* __restrict__ cth, __nv_bfloat16* __restrict__ ctl)
{
    const int bid = blockIdx.x;
    if (bid < 32) {
        tsplit_body(W_feat, wfh, wfl, DDIM, ADIM, bid);
    } else if (bid < 48) {
        tsplit_body(Wpsi2, wph, wpl, HIDD, DDIM, bid - 32);
    } else if (bid < 54) {
        int c = (bid - 48) * 256 + threadIdx.x;
        if (c < DSUM) {
            if (c < 256)      bcat[c] = bt[c];
            else if (c < 512) bcat[c] = bc[c - 256];
            else              bcat[c] = be[c - 512];
        }
    } else {
        // lf split into concat cols [768, 1536)
        int i4 = (bid - 54) * 256 + threadIdx.x;     // float4 idx over lf (786432)
        int n = i4 / 192;
        int c = (i4 - n * 192) * 4;
        float4 v = ((const float4*)lf)[i4];
        size_t e = (size_t)n * DSUM + 768 + c;
        split_store(v.x, cth + e + 0, ctl + e + 0);
        split_store(v.y, cth + e + 1, ctl + e + 1);
        split_store(v.z, cth + e + 2, ctl + e + 2);
        split_store(v.w, cth + e + 3, ctl + e + 3);
    }
}

// prep3: Wres (2304) + W1 (96) + Wo (384) + Wpsi1^T (1024) tsplits
__global__ void prep3_kernel(const float* __restrict__ Wres,
                             __nv_bfloat16* __restrict__ wrh, __nv_bfloat16* __restrict__ wrl,
                             const float* __restrict__ W1,
                             __nv_bfloat16* __restrict__ w1h, __nv_bfloat16* __restrict__ w1l,
                             const float* __restrict__ Wo,
                             __nv_bfloat16* __restrict__ woh, __nv_bfloat16* __restrict__ wol,
                             const float* __restrict__ Wpsi1,
                             __nv_bfloat16* __restrict__ wp1h, __nv_bfloat16* __restrict__ wp1l)
{
    const int bid = blockIdx.x;
    if (bid < 2304)      tsplit_body(Wres, wrh, wrl, DSUM, DSUM, bid);
    else if (bid < 2400) tsplit_body(W1, w1h, w1l, DSUM, HIDD, bid - 2304);
    else if (bid < 2784) tsplit_body(Wo, woh, wol, DSUM, DDIM, bid - 2400);
    else                 tsplit_body(Wpsi1, wp1h, wp1l, 16384, HIDD, bid - 2784);
}

// ---------------------------------------------------------------------------
// GEMM body: HMMA bf16 3-split, 3-stage cp.async ring.
// EPI: 0 = fp32 C + bias; 1 = fp32 + bias + gelu; 2 = bf16 split (Ch/Cl, stride N);
//      3 = MoE epilogue (bias=bpsi2, uses mixp/gatep, writes Ch/Cl cols 512+).
// ---------------------------------------------------------------------------
template <int BM, int BN, int EPI>
__device__ __forceinline__ void
gemm_body(const __nv_bfloat16* __restrict__ Ahi, const __nv_bfloat16* __restrict__ Alo,
          const __nv_bfloat16* __restrict__ BThi, const __nv_bfloat16* __restrict__ BTlo,
          const float* __restrict__ bias, float* __restrict__ C,
          __nv_bfloat16* __restrict__ Ch, __nv_bfloat16* __restrict__ Cl,
          const float* __restrict__ mixp, const float* __restrict__ gatep,
          int M, int N, int K, int bm, int bn, char* smem_raw)
{
    constexpr int ASZ = BM * 128;
    constexpr int BSZ = BN * 128;
    constexpr int STG = ASZ + BSZ;
    constexpr int WM  = BM / 64;
    constexpr int WN  = 8 / WM;
    constexpr int WTN = BN / WN;
    constexpr int NF  = WTN / 8;

    const uint32_t tile0 = (smem_to_u32(smem_raw) + 1023) & ~1023u;

    const int tid = threadIdx.x;
    const int wid = tid >> 5, lane = tid & 31;
    const int wm = (WM == 1) ? 0 : (wid & 1);
    const int wn = (WM == 1) ? wid : (wid >> 1);
    const int KC = K >> 6;
    const int NC = 3 * KC;

    float acc[4][NF][4];
#pragma unroll
    for (int mf = 0; mf < 4; mf++)
#pragma unroll
        for (int nf = 0; nf < NF; nf++)
#pragma unroll
            for (int i = 0; i < 4; i++) acc[mf][nf][i] = 0.f;

    auto stage = [&](int c) {
        const int buf = c % 3;
        const int blk = c / KC;
        const int k0  = (c - blk * KC) << 6;
        const __nv_bfloat16* Asrc = ((blk < 2) ? Ahi : Alo) + (size_t)bm * K + k0;
        const __nv_bfloat16* Bsrc = ((blk == 1) ? BTlo : BThi) + (size_t)bn * K + k0;
        const uint32_t ab = tile0 + buf * STG;
        const uint32_t bb = ab + ASZ;
#pragma unroll
        for (int i = 0; i < BM / 32; i++) {
            int u = i * 256 + tid;
            int row = u >> 3, seg = u & 7;
            uint32_t off = row * 128 + seg * 16;
            cp_async16(ab + SMEM_SWIZZLE_128B(off), Asrc + (size_t)row * K + seg * 8);
        }
#pragma unroll
        for (int i = 0; i < BN / 32; i++) {
            int u = i * 256 + tid;
            int row = u >> 3, seg = u & 7;
            uint32_t off = row * 128 + seg * 16;
            cp_async16(bb + SMEM_SWIZZLE_128B(off), Bsrc + (size_t)row * K + seg * 8);
        }
    };

    auto compute = [&](int buf) {
        const uint32_t ab = tile0 + buf * STG;
        const uint32_t bb = ab + ASZ;
#pragma unroll
        for (int k16 = 0; k16 < 4; k16++) {
            uint32_t ar[4][4];
#pragma unroll
            for (int mf = 0; mf < 4; mf++) {
                int row = wm * 64 + mf * 16 + (lane & 15);
                uint32_t off = row * 128 + k16 * 32 + ((lane >> 4) << 4);
                ldsm_x4(ab + SMEM_SWIZZLE_128B(off), ar[mf][0], ar[mf][1], ar[mf][2], ar[mf][3]);
            }
            uint32_t br[NF][2];
            if (NF == 1) {
                int n = wn * WTN + (lane & 7);
                uint32_t off = n * 128 + k16 * 32 + (((lane >> 3) & 1) << 4);
                ldsm_x2(bb + SMEM_SWIZZLE_128B(off), br[0][0], br[0][1]);
            } else {
#pragma unroll
                for (int nb = 0; nb < NF / 2; nb++) {
                    int grp = lane >> 3;
                    int n = wn * WTN + nb * 16 + ((grp >> 1) << 3) + (lane & 7);
                    uint32_t off = n * 128 + k16 * 32 + ((grp & 1) << 4);
                    ldsm_x4(bb + SMEM_SWIZZLE_128B(off),
                            br[2*nb][0], br[2*nb][1], br[2*nb+1][0], br[2*nb+1][1]);
                }
            }
#pragma unroll
            for (int mf = 0; mf < 4; mf++)
#pragma unroll
                for (int nf = 0; nf < NF; nf++)
                    mma16816(acc[mf][nf][0], acc[mf][nf][1], acc[mf][nf][2], acc[mf][nf][3],
                             ar[mf][0], ar[mf][1], ar[mf][2], ar[mf][3],
                             br[nf][0], br[nf][1]);
        }
    };

    stage(0); CP_COMMIT();
    if (NC > 1) { stage(1); CP_COMMIT(); }
    for (int c = 0; c < NC; c++) {
        if (c + 1 < NC) CP_WAIT1(); else CP_WAIT0();
        __syncthreads();
        if (c + 2 < NC) { stage(c + 2); CP_COMMIT(); }
        compute(c % 3);
    }

    if (EPI == 3) {
        // MoE epilogue (BM=64, NF=1): ka value -> moe -> split into cols 512+
        int col = bn + wn * WTN + ((lane & 3) << 1);
        float2 bv = *(const float2*)(bias + col);
#pragma unroll
        for (int mf = 0; mf < 4; mf++) {
            int r0 = bm + mf * 16 + (lane >> 2);
#pragma unroll
            for (int rr = 0; rr < 2; rr++) {
                int r = r0 + rr * 8;
                float ka0 = acc[mf][0][rr * 2 + 0] + bv.x;
                float ka1 = acc[mf][0][rr * 2 + 1] + bv.y;
                float g0 = __ldg(gatep + r * 5 + 0);
                float g1 = __ldg(gatep + r * 5 + 1);
                float g2 = __ldg(gatep + r * 5 + 2);
                float g3 = __ldg(gatep + r * 5 + 3);
                float g4 = __ldg(gatep + r * 5 + 4);
                const float* mrow = mixp + (size_t)r * DSUM + 512 + col;
                float m0 = g0 * mrow[0] + g1 * mrow[256] + g2 * mrow[512]
                         + g3 * mrow[768] + g4 * ka0;
                float m1 = g0 * mrow[1] + g1 * mrow[257] + g2 * mrow[513]
                         + g3 * mrow[769] + g4 * ka1;
                size_t e = (size_t)r * DSUM + 512 + col;
                split_store(m0, Ch + e,     Cl + e);
                split_store(m1, Ch + e + 1, Cl + e + 1);
            }
        }
    } else {
#pragma unroll
        for (int nf = 0; nf < NF; nf++) {
            int col = bn + wn * WTN + nf * 8 + ((lane & 3) << 1);
            float2 bv = *(const float2*)(bias + col);
#pragma unroll
            for (int mf = 0; mf < 4; mf++) {
                int row = bm + wm * 64 + mf * 16 + (lane >> 2);
                float x0 = acc[mf][nf][0] + bv.x;
                float x1 = acc[mf][nf][1] + bv.y;
                float x2 = acc[mf][nf][2] + bv.x;
                float x3 = acc[mf][nf][3] + bv.y;
                if (EPI == 1) { x0 = gelu_f(x0); x1 = gelu_f(x1); x2 = gelu_f(x2); x3 = gelu_f(x3); }
                if (EPI == 2) {
                    size_t e0 = (size_t)row * N + col;
                    size_t e1 = (size_t)(row + 8) * N + col;
                    split_store(x0, Ch + e0,     Cl + e0);
                    split_store(x1, Ch + e0 + 1, Cl + e0 + 1);
                    split_store(x2, Ch + e1,     Cl + e1);
                    split_store(x3, Ch + e1 + 1, Cl + e1 + 1);
                } else {
                    *(float2*)&C[(size_t)row * N + col]       = make_float2(x0, x1);
                    *(float2*)&C[(size_t)(row + 8) * N + col] = make_float2(x2, x3);
                }
            }
        }
    }
}

// standalone GEMM kernel wrapper
template <int BM, int BN, int EPI>
__global__ void __launch_bounds__(256, 2)
gemm_hmma(const __nv_bfloat16* __restrict__ Ahi, const __nv_bfloat16* __restrict__ Alo,
          const __nv_bfloat16* __restrict__ BThi, const __nv_bfloat16* __restrict__ BTlo,
          const float* __restrict__ bias, float* __restrict__ C,
          int M, int N, int K)
{
    extern __shared__ char smem_raw[];
    gemm_body<BM, BN, EPI>(Ahi, Alo, BThi, BTlo, bias, C,
                           nullptr, nullptr, nullptr, nullptr,
                           M, N, K, blockIdx.y * BM, blockIdx.x * BN, smem_raw);
}

// ka2 + moe epilogue: cth/ctl cols 512..767 = sum_e gate_e*mix_e + gate4*(tpsi@Wpsi2+bpsi2)
__global__ void __launch_bounds__(256, 2)
ka2_moe_kernel(const __nv_bfloat16* __restrict__ tph, const __nv_bfloat16* __restrict__ tpl,
               const __nv_bfloat16* __restrict__ wph, const __nv_bfloat16* __restrict__ wpl,
               const float* __restrict__ bpsi2, const float* __restrict__ mix,
               const float* __restrict__ gate,
               __nv_bfloat16* __restrict__ cth, __nv_bfloat16* __restrict__ ctl)
{
    extern __shared__ char smem_raw[];
    gemm_body<64, 64, 3>(tph, tpl, wph, wpl, bpsi2, nullptr,
                         cth, ctl, mix, gate,
                         NTOK, DDIM, HIDD, blockIdx.y * 64, blockIdx.x * 64, smem_raw);
}

// ---------------------------------------------------------------------------
// gemm3c_body: stage-once / 3-combo 128x128 GEMM, 3-stage ring.
// ---------------------------------------------------------------------------
__device__ __forceinline__ void
gemm3c_body(const __nv_bfloat16* __restrict__ Ahi, const __nv_bfloat16* __restrict__ Alo,
            const __nv_bfloat16* __restrict__ BThi, const __nv_bfloat16* __restrict__ BTlo,
            const float* __restrict__ bias, float* __restrict__ C,
            int N, int K, int bm, int bn, char* smem_raw)
{
    constexpr int TSZ = 128 * 128;
    constexpr int STG = 4 * TSZ;

    const uint32_t tile0 = (smem_to_u32(smem_raw) + 1023) & ~1023u;

    const int tid = threadIdx.x;
    const int wid = tid >> 5, lane = tid & 31;
    const int wm = wid & 1, wn = wid >> 1;
    const int NC = K >> 6;

    float acc[4][4][4];
#pragma unroll
    for (int mf = 0; mf < 4; mf++)
#pragma unroll
        for (int nf = 0; nf < 4; nf++)
#pragma unroll
            for (int i = 0; i < 4; i++) acc[mf][nf][i] = 0.f;

    auto stage = [&](int c) {
        const int k0 = c << 6;
        const uint32_t sb = tile0 + (c % 3) * STG;
        const __nv_bfloat16* srcs[4] = {
            Ahi + (size_t)bm * K + k0, Alo + (size_t)bm * K + k0,
            BThi + (size_t)bn * K + k0, BTlo + (size_t)bn * K + k0 };
#pragma unroll
        for (int t = 0; t < 4; t++) {
            const __nv_bfloat16* src = srcs[t];
            const uint32_t dst = sb + t * TSZ;
#pragma unroll
            for (int i = 0; i < 4; i++) {
                int u = i * 256 + tid;
                int row = u >> 3, seg = u & 7;
                uint32_t off = row * 128 + seg * 16;
                cp_async16(dst + SMEM_SWIZZLE_128B(off), src + (size_t)row * K + seg * 8);
            }
        }
    };

    auto compute = [&](int buf) {
        const uint32_t ah = tile0 + buf * STG;
        const uint32_t al = ah + TSZ;
        const uint32_t bh = ah + 2 * TSZ;
        const uint32_t bl = ah + 3 * TSZ;
#pragma unroll
        for (int k16 = 0; k16 < 4; k16++) {
            uint32_t Ah[4][4], Al[4][4], Bh[4][2], Bl[4][2];
#pragma unroll
            for (int mf = 0; mf < 4; mf++) {
                int row = wm * 64 + mf * 16 + (lane & 15);
                uint32_t off = SMEM_SWIZZLE_128B(
                    (uint32_t)(row * 128 + k16 * 32 + ((lane >> 4) << 4)));
                ldsm_x4(ah + off, Ah[mf][0], Ah[mf][1], Ah[mf][2], Ah[mf][3]);
                ldsm_x4(al + off, Al[mf][0], Al[mf][1], Al[mf][2], Al[mf][3]);
            }
#pragma unroll
            for (int nb = 0; nb < 2; nb++) {
                int grp = lane >> 3;
                int n = wn * 32 + nb * 16 + ((grp >> 1) << 3) + (lane & 7);
                uint32_t off = SMEM_SWIZZLE_128B(
                    (uint32_t)(n * 128 + k16 * 32 + ((grp & 1) << 4)));
                ldsm_x4(bh + off, Bh[2*nb][0], Bh[2*nb][1], Bh[2*nb+1][0], Bh[2*nb+1][1]);
                ldsm_x4(bl + off, Bl[2*nb][0], Bl[2*nb][1], Bl[2*nb+1][0], Bl[2*nb+1][1]);
            }
#pragma unroll
            for (int mf = 0; mf < 4; mf++)
#pragma unroll
                for (int nf = 0; nf < 4; nf++)
                    mma16816(acc[mf][nf][0], acc[mf][nf][1], acc[mf][nf][2], acc[mf][nf][3],
                             Ah[mf][0], Ah[mf][1], Ah[mf][2], Ah[mf][3],
                             Bh[nf][0], Bh[nf][1]);
#pragma unroll
            for (int mf = 0; mf < 4; mf++)
#pragma unroll
                for (int nf = 0; nf < 4; nf++)
                    mma16816(acc[mf][nf][0], acc[mf][nf][1], acc[mf][nf][2], acc[mf][nf][3],
                             Ah[mf][0], Ah[mf][1], Ah[mf][2], Ah[mf][3],
                             Bl[nf][0], Bl[nf][1]);
#pragma unroll
            for (int mf = 0; mf < 4; mf++)
#pragma unroll
                for (int nf = 0; nf < 4; nf++)
                    mma16816(acc[mf][nf][0], acc[mf][nf][1], acc[mf][nf][2], acc[mf][nf][3],
                             Al[mf][0], Al[mf][1], Al[mf][2], Al[mf][3],
                             Bh[nf][0], Bh[nf][1]);
        }
    };

    stage(0); CP_COMMIT();
    if (NC > 1) { stage(1); CP_COMMIT(); }
    for (int c = 0; c < NC; c++) {
        if (c + 1 < NC) CP_WAIT1(); else CP_WAIT0();
        __syncthreads();
        if (c + 2 < NC) { stage(c + 2); CP_COMMIT(); }
        compute(c % 3);
    }

#pragma unroll
    for (int nf = 0; nf < 4; nf++) {
        int col = bn + wn * 32 + nf * 8 + ((lane & 3) << 1);
        float2 bv = *(const float2*)(bias + col);
#pragma unroll
        for (int mf = 0; mf < 4; mf++) {
            int row = bm + wm * 64 + mf * 16 + (lane >> 2);
            *(float2*)&C[(size_t)row * N + col] =
                make_float2(acc[mf][nf][0] + bv.x, acc[mf][nf][1] + bv.y);
            *(float2*)&C[(size_t)(row + 8) * N + col] =
                make_float2(acc[mf][nf][2] + bv.x, acc[mf][nf][3] + bv.y);
        }
    }
}

// ---------------------------------------------------------------------------
// KA stage-1, HMMA version.
// ---------------------------------------------------------------------------
__device__ __forceinline__ void
ka_hmma_body(const float* __restrict__ xf, const float* __restrict__ Wphi,
             const float* __restrict__ bphi,
             const __nv_bfloat16* __restrict__ wp1h, const __nv_bfloat16* __restrict__ wp1l,
             float* __restrict__ kapart, int b, char* smem_raw)
{
    const uint32_t base = smem_to_u32(smem_raw);
    const uint32_t tile0 = (base + 1023) & ~1023u;
    char* cbase = smem_raw + (tile0 - base);

    const uint32_t PH = 32768, PL = 40960;
    float* xs  = (float*)(cbase + 49152);
    float* wps = (float*)(cbase + 65792);
    float* bps = (float*)(cbase + 82176);

    const int tid = threadIdx.x;
    const int s   = b & 3;
    const int t0  = (b >> 2) << 6;

    {
        int tok = tid >> 2, dq = (tid & 3) << 4;
        const float* xp = xf + (size_t)(t0 + tok) * 256 + (s << 6) + dq;
#pragma unroll
        for (int j = 0; j < 16; j += 4) {
            float4 v = *(const float4*)(xp + j);
            xs[(dq + j + 0) * 65 + tok] = v.x;
            xs[(dq + j + 1) * 65 + tok] = v.y;
            xs[(dq + j + 2) * 65 + tok] = v.z;
            xs[(dq + j + 3) * 65 + tok] = v.w;
        }
        const float4* wsrc = (const float4*)(Wphi + (s << 12));
        const float4* bsrc = (const float4*)(bphi + (s << 12));
        float4* wdst = (float4*)wps;
        float4* bdst = (float4*)bps;
#pragma unroll
        for (int r = 0; r < 4; r++) {
            wdst[tid + (r << 8)] = wsrc[tid + (r << 8)];
            bdst[tid + (r << 8)] = bsrc[tid + (r << 8)];
        }
    }

    auto stageB = [&](int d) {
        const uint32_t dsth = tile0 + (d & 1) * 16384;
        const uint32_t dstl = dsth + 8192;
        const __nv_bfloat16* sh = wp1h + (s << 12) + (d << 6);
        const __nv_bfloat16* sl = wp1l + (s << 12) + (d << 6);
#pragma unroll
        for (int i = 0; i < 2; i++) {
            int u = i * 256 + tid;
            int row = u >> 3, seg = u & 7;
            uint32_t off = SMEM_SWIZZLE_128B((uint32_t)(row * 128 + seg * 16));
            cp_async16(dsth + off, sh + (size_t)row * 16384 + seg * 8);
            cp_async16(dstl + off, sl + (size_t)row * 16384 + seg * 8);
        }
    };

    stageB(0); CP_COMMIT();
    __syncthreads();

    const int wid = tid >> 5, lane = tid & 31;
    const int wm = wid & 1, wn = wid >> 1;
    const int ptok = tid & 63, hq = tid >> 6;

    float acc[2][2][4];
#pragma unroll
    for (int mf = 0; mf < 2; mf++)
#pragma unroll
        for (int nf = 0; nf < 2; nf++)
#pragma unroll
            for (int i = 0; i < 4; i++) acc[mf][nf][i] = 0.f;

    for (int d = 0; d < 64; d++) {
        if (d + 1 < 64) { stageB(d + 1); CP_COMMIT(); }
        {
            float xv = xs[d * 65 + ptok];
            const float* wr = wps + (d << 6);
            const float* br2 = bps + (d << 6);
#pragma unroll
            for (int j = 0; j < 16; j += 2) {
                int h = (hq << 4) + j;
                float v0 = gelu_f(fmaf(xv, wr[h],     br2[h]));
                float v1 = gelu_f(fmaf(xv, wr[h + 1], br2[h + 1]));
                __nv_bfloat16 h0 = __float2bfloat16(v0);
                __nv_bfloat16 h1 = __float2bfloat16(v1);
                __nv_bfloat162 hp(h0, h1);
                __nv_bfloat162 lp(__float2bfloat16(v0 - __bfloat162float(h0)),
                                  __float2bfloat16(v1 - __bfloat162float(h1)));
                uint32_t off = SMEM_SWIZZLE_128B((uint32_t)(ptok * 128 + h * 2));
                *(__nv_bfloat162*)(cbase + PH + off) = hp;
                *(__nv_bfloat162*)(cbase + PL + off) = lp;
            }
        }
        if (d + 1 < 64) CP_WAIT1(); else CP_WAIT0();
        __syncthreads();
        {
            const uint32_t bh = tile0 + (d & 1) * 16384;
            const uint32_t bl = bh + 8192;
            const uint32_t ah = tile0 + PH, al = tile0 + PL;
#pragma unroll
            for (int k16 = 0; k16 < 4; k16++) {
                uint32_t Ah[2][4], Al[2][4], Bh[2][2], Bl[2][2];
#pragma unroll
                for (int mf = 0; mf < 2; mf++) {
                    int row = wm * 32 + mf * 16 + (lane & 15);
                    uint32_t off = SMEM_SWIZZLE_128B(
                        (uint32_t)(row * 128 + k16 * 32 + ((lane >> 4) << 4)));
                    ldsm_x4(ah + off, Ah[mf][0], Ah[mf][1], Ah[mf][2], Ah[mf][3]);
                    ldsm_x4(al + off, Al[mf][0], Al[mf][1], Al[mf][2], Al[mf][3]);
                }
                {
                    int grp = lane >> 3;
                    int n = wn * 16 + ((grp >> 1) << 3) + (lane & 7);
                    uint32_t off = SMEM_SWIZZLE_128B(
                        (uint32_t)(n * 128 + k16 * 32 + ((grp & 1) << 4)));
                    ldsm_x4(bh + off, Bh[0][0], Bh[0][1], Bh[1][0], Bh[1][1]);
                    ldsm_x4(bl + off, Bl[0][0], Bl[0][1], Bl[1][0], Bl[1][1]);
                }
#pragma unroll
                for (int mf = 0; mf < 2; mf++)
#pragma unroll
                    for (int nf = 0; nf < 2; nf++) {
                        mma16816(acc[mf][nf][0], acc[mf][nf][1], acc[mf][nf][2], acc[mf][nf][3],
                                 Ah[mf][0], Ah[mf][1], Ah[mf][2], Ah[mf][3],
                                 Bh[nf][0], Bh[nf][1]);
                        mma16816(acc[mf][nf][0], acc[mf][nf][1], acc[mf][nf][2], acc[mf][nf][3],
                                 Al[mf][0], Al[mf][1], Al[mf][2], Al[mf][3],
                                 Bh[nf][0], Bh[nf][1]);
                        mma16816(acc[mf][nf][0], acc[mf][nf][1], acc[mf][nf][2], acc[mf][nf][3],
                                 Ah[mf][0], Ah[mf][1], Ah[mf][2], Ah[mf][3],
                                 Bl[nf][0], Bl[nf][1]);
                    }
            }
        }
        __syncthreads();
    }

    float* pout = kapart + (size_t)s * (NTOK * HIDD) + (size_t)t0 * HIDD;
#pragma unroll
    for (int mf = 0; mf < 2; mf++)
#pragma unroll
        for (int nf = 0; nf < 2; nf++) {
            int row = wm * 32 + mf * 16 + (lane >> 2);
            int col = wn * 16 + nf * 8 + ((lane & 3) << 1);
            *(float2*)&pout[(size_t)row * HIDD + col] =
                make_float2(acc[mf][nf][0], acc[mf][nf][1]);
            *(float2*)&pout[(size_t)(row + 8) * HIDD + col] =
                make_float2(acc[mf][nf][2], acc[mf][nf][3]);
        }
}

// ---------------------------------------------------------------------------
// Fused kernels
// ---------------------------------------------------------------------------
__global__ void __launch_bounds__(256, 2)
fused_mix_ka(const __nv_bfloat16* __restrict__ xh, const __nv_bfloat16* __restrict__ xl,
             const __nv_bfloat16* __restrict__ wdh, const __nv_bfloat16* __restrict__ wdl,
             const float* __restrict__ bcat, float* __restrict__ mix,
             __nv_bfloat16* __restrict__ cth, __nv_bfloat16* __restrict__ ctl,
             const float* __restrict__ xf, const float* __restrict__ Wphi,
             const float* __restrict__ bphi,
             const __nv_bfloat16* __restrict__ wp1h, const __nv_bfloat16* __restrict__ wp1l,
             float* __restrict__ kapart)
{
    extern __shared__ char smem_raw[];
    const int bid = blockIdx.x;
    if (bid < 384) {
        const int bnt = bid % 12;
        const int bm = (bid / 12) * 128, bn = bnt * 128;
        if (bnt < 4)    // tok/chan columns -> direct bf16 split into concat
            gemm_body<128, 128, 2>(xh, xl, wdh, wdl, bcat, nullptr,
                                   cth, ctl, nullptr, nullptr,
                                   NTOK, DSUM, DDIM, bm, bn, smem_raw);
        else            // expert columns -> fp32 mix
            gemm_body<128, 128, 0>(xh, xl, wdh, wdl, bcat, mix,
                                   nullptr, nullptr, nullptr, nullptr,
                                   NTOK, DSUM, DDIM, bm, bn, smem_raw);
    } else {
        ka_hmma_body(xf, Wphi, bphi, wp1h, wp1l, kapart, bid - 384, smem_raw);
    }
}

// resid via stage-once/3-combo 3-stage ring (384 blocks) + h GEMM (64 blocks)
__global__ void __launch_bounds__(256)
fused_resid_h(const __nv_bfloat16* __restrict__ cth, const __nv_bfloat16* __restrict__ ctl,
              const __nv_bfloat16* __restrict__ wrh, const __nv_bfloat16* __restrict__ wrl,
              const float* __restrict__ bres, float* __restrict__ resid,
              const __nv_bfloat16* __restrict__ w1h, const __nv_bfloat16* __restrict__ w1l,
              const float* __restrict__ b1, float* __restrict__ hbuf)
{
    extern __shared__ char smem_raw[];
    const int bid = blockIdx.x;
    if (bid < 384) {
        gemm3c_body(cth, ctl, wrh, wrl, bres, resid,
                    DSUM, DSUM,
                    (bid / 12) * 128, (bid % 12) * 128, smem_raw);
    } else {
        gemm_body<64, 64, 1>(cth, ctl, w1h, w1l, b1, hbuf,
                             nullptr, nullptr, nullptr, nullptr,
                             NTOK, HIDD, DSUM, (bid - 384) * 64, 0, smem_raw);
    }
}

// ---------------------------------------------------------------------------
// am = mean over tokens of adapt
// ---------------------------------------------------------------------------
__global__ void colsum_part_kernel(const float* __restrict__ adapt, float* __restrict__ part)
{
    const int j = threadIdx.x;
    const int b = blockIdx.x;
    float s = 0.f;
#pragma unroll 8
    for (int r = 0; r < 128; r++) s += adapt[(size_t)(b * 128 + r) * ADIM + j];
    part[b * ADIM + j] = s;
}
__global__ void colsum_fin_kernel(const float* __restrict__ part, float* __restrict__ am)
{
    const int j = threadIdx.x;
    float s = 0.f;
#pragma unroll
    for (int b = 0; b < 32; b++) s += part[b * ADIM + j];
    am[j] = s * (1.0f / (float)NTOK);
}

// ---------------------------------------------------------------------------
// Dynamic weights
// ---------------------------------------------------------------------------
__global__ void dynw_kernel(const float* __restrict__ Wt,  const float* __restrict__ Wt_a, const float* __restrict__ bt_a,
                            const float* __restrict__ Wc,  const float* __restrict__ Wc_a, const float* __restrict__ bc_a,
                            const float* __restrict__ We,  const float* __restrict__ We_a, const float* __restrict__ be_a,
                            const float* __restrict__ am,  float* __restrict__ Wdyn)
{
    __shared__ float ams[ADIM];
    const int tid = threadIdx.x;
    if (tid < ADIM) ams[tid] = am[tid];
    __syncthreads();

    const int idx4 = blockIdx.x * 256 + tid;
    const int k    = idx4 / 384;
    const int c4   = (idx4 - k * 384) * 4;

    const float *Wa, *ba, *base;
    int m;
    if (c4 < 256)      { m = k * 256 + c4;          base = Wt; Wa = Wt_a; ba = bt_a; }
    else if (c4 < 512) { m = k * 256 + (c4 - 256);  base = Wc; Wa = Wc_a; ba = bc_a; }
    else {
        int e  = (c4 - 512) >> 8;
        int jj = (c4 - 512) & 255;
        m = k * 256 + jj;
        base = We + e * 65536;
        Wa   = We_a + (size_t)e * 8388608u;
        ba   = be_a + e * 65536;
    }
    float4 acc = *(const float4*)(base + m);
    float4 b4  = *(const float4*)(ba + m);
    acc.x += b4.x; acc.y += b4.y; acc.z += b4.z; acc.w += b4.w;
#pragma unroll 4
    for (int a = 0; a < ADIM; a++) {
        float s = ams[a];
        float4 w = *(const float4*)(Wa + (size_t)a * 65536 + m);
        acc.x = fmaf(s, w.x, acc.x);
        acc.y = fmaf(s, w.y, acc.y);
        acc.z = fmaf(s, w.z, acc.z);
        acc.w = fmaf(s, w.w, acc.w);
    }
    *(float4*)(Wdyn + (size_t)idx4 * 4) = acc;
}

// ---------------------------------------------------------------------------
// gate = softmax(adapt @ Wg + bg)
// ---------------------------------------------------------------------------
__global__ void gate_kernel(const float* __restrict__ adapt, const float* __restrict__ Wg,
                            const float* __restrict__ bg, float* __restrict__ gate)
{
    __shared__ float wgs[ADIM * 5];
    __shared__ float bgs[5];
    const int tid = threadIdx.x;
    for (int i = tid; i < ADIM * 5; i += 256) wgs[i] = Wg[i];
    if (tid < 5) bgs[tid] = bg[tid];
    __syncthreads();

    const int warp = tid >> 5, lane = tid & 31;
    const int n = (blockIdx.x << 3) + warp;

    float4 a4 = *(const float4*)(adapt + (size_t)n * ADIM + lane * 4);
    float av[4] = { a4.x, a4.y, a4.z, a4.w };
    float l[5] = { 0, 0, 0, 0, 0 };
#pragma unroll
    for (int q = 0; q < 4; q++) {
        int a = lane * 4 + q;
#pragma unroll
        for (int j = 0; j < 5; j++) l[j] = fmaf(av[q], wgs[a * 5 + j], l[j]);
    }
#pragma unroll
    for (int off = 16; off; off >>= 1)
#pragma unroll
        for (int j = 0; j < 5; j++) l[j] += __shfl_xor_sync(0xffffffffu, l[j], off);

    if (lane == 0) {
#pragma unroll
        for (int j = 0; j < 5; j++) l[j] += bgs[j];
        float mx = fmaxf(fmaxf(fmaxf(l[0], l[1]), fmaxf(l[2], l[3])), l[4]);
        float s = 0.f;
#pragma unroll
        for (int j = 0; j < 5; j++) { l[j] = __expf(l[j] - mx); s += l[j]; }
        float inv = 1.0f / s;
#pragma unroll
        for (int j = 0; j < 5; j++) gate[n * 5 + j] = l[j] * inv;
    }
}

// tpsi = gelu(sum of 4 partials + bpsi1) -> bf16 hi/lo
__global__ void ka_finish_kernel(const float* __restrict__ part,
                                 const float* __restrict__ bpsi1,
                                 __nv_bfloat16* __restrict__ tph,
                                 __nv_bfloat16* __restrict__ tpl)
{
    const int idx = blockIdx.x * 256 + threadIdx.x;
    const int jq = idx & 15;
    const float4* p = (const float4*)part;
    float4 a = p[idx];
    float4 b = p[65536 + idx];
    float4 c = p[131072 + idx];
    float4 d = p[196608 + idx];
    float4 bb = ((const float4*)bpsi1)[jq];
    float o[4];
    o[0] = gelu_f(a.x + b.x + c.x + d.x + bb.x);
    o[1] = gelu_f(a.y + b.y + c.y + d.y + bb.y);
    o[2] = gelu_f(a.z + b.z + c.z + d.z + bb.z);
    o[3] = gelu_f(a.w + b.w + c.w + d.w + bb.w);
#pragma unroll
    for (int q = 0; q < 4; q++) split_store(o[q], tph + idx * 4 + q, tpl + idx * 4 + q);
}

// ---------------------------------------------------------------------------
// combine: cw = softmax(h @ W2 + b2); comb = cw*(cth+ctl) + resid (bf16 out)
// ---------------------------------------------------------------------------
__global__ void combine_kernel(const float* __restrict__ h, const float* __restrict__ W2,
                               const float* __restrict__ b2,
                               const __nv_bfloat16* __restrict__ cth,
                               const __nv_bfloat16* __restrict__ ctl,
                               const float* __restrict__ resid,
                               __nv_bfloat16* __restrict__ cbh, __nv_bfloat16* __restrict__ cbl)
{
    __shared__ float w2s[256];
    const int tid = threadIdx.x;
    w2s[tid] = W2[tid];
    __syncthreads();

    const int warp = tid >> 5, lane = tid & 31;
    const int n = (blockIdx.x << 3) + warp;

    float2 hv = *(const float2*)(h + (size_t)n * HIDD + lane * 2);
    const int a0 = lane * 2, a1 = lane * 2 + 1;
    float l0 = hv.x * w2s[a0*4+0] + hv.y * w2s[a1*4+0];
    float l1 = hv.x * w2s[a0*4+1] + hv.y * w2s[a1*4+1];
    float l2 = hv.x * w2s[a0*4+2] + hv.y * w2s[a1*4+2];
    float l3 = hv.x * w2s[a0*4+3] + hv.y * w2s[a1*4+3];
#pragma unroll
    for (int off = 16; off; off >>= 1) {
        l0 += __shfl_xor_sync(0xffffffffu, l0, off);
        l1 += __shfl_xor_sync(0xffffffffu, l1, off);
        l2 += __shfl_xor_sync(0xffffffffu, l2, off);
        l3 += __shfl_xor_sync(0xffffffffu, l3, off);
    }
    l0 += __ldg(b2 + 0); l1 += __ldg(b2 + 1); l2 += __ldg(b2 + 2); l3 += __ldg(b2 + 3);
    float mx = fmaxf(fmaxf(l0, l1), fmaxf(l2, l3));
    float e0 = __expf(l0 - mx), e1 = __expf(l1 - mx), e2 = __expf(l2 - mx), e3 = __expf(l3 - mx);
    float inv = 1.0f / (e0 + e1 + e2 + e3);
    float cw0 = e0 * inv, cw1 = e1 * inv, cw2 = e2 * inv, cw3 = e3 * inv;

    const __nv_bfloat162* ch = (const __nv_bfloat162*)(cth + (size_t)n * DSUM);
    const __nv_bfloat162* cl = (const __nv_bfloat162*)(ctl + (size_t)n * DSUM);
    const float4* rr = (const float4*)(resid + (size_t)n * DSUM);
#pragma unroll
    for (int q = 0; q < 12; q++) {
        int c4 = lane + (q << 5);
        float w = (c4 < 64) ? cw0 : (c4 < 128) ? cw1 : (c4 < 192) ? cw2 : cw3;
        __nv_bfloat162 h01 = ch[2 * c4], h23 = ch[2 * c4 + 1];
        __nv_bfloat162 l01 = cl[2 * c4], l23 = cl[2 * c4 + 1];
        float cx = __bfloat162float(h01.x) + __bfloat162float(l01.x);
        float cy = __bfloat162float(h01.y) + __bfloat162float(l01.y);
        float cz = __bfloat162float(h23.x) + __bfloat162float(l23.x);
        float cw_ = __bfloat162float(h23.y) + __bfloat162float(l23.y);
        float4 rv = rr[c4];
        float v0 = fmaf(w, cx, rv.x), v1 = fmaf(w, cy, rv.y);
        float v2 = fmaf(w, cz, rv.z), v3 = fmaf(w, cw_, rv.w);
        const size_t e = (size_t)n * DSUM + c4 * 4;
        split_store(v0, cbh + e + 0, cbl + e + 0);
        split_store(v1, cbh + e + 1, cbl + e + 1);
        split_store(v2, cbh + e + 2, cbl + e + 2);
        split_store(v3, cbh + e + 3, cbl + e + 3);
    }
}

// ---------------------------------------------------------------------------
// Host launcher
// ---------------------------------------------------------------------------
extern "C" void kernel_launch(void* const* d_in, const int* in_sizes, int n_in,
                              void* d_out, int out_size)
{
    (void)in_sizes; (void)n_in; (void)out_size;

    const float* x      = (const float*)d_in[0];
    const float* lf     = (const float*)d_in[1];
    const float* W_feat = (const float*)d_in[2];
    const float* b_feat = (const float*)d_in[3];
    const float* Wt     = (const float*)d_in[4];
    const float* bt     = (const float*)d_in[5];
    const float* Wt_a   = (const float*)d_in[6];
    const float* bt_a   = (const float*)d_in[7];
    const float* Wc     = (const float*)d_in[8];
    const float* bc     = (const float*)d_in[9];
    const float* Wc_a   = (const float*)d_in[10];
    const float* bc_a   = (const float*)d_in[11];
    const float* We     = (const float*)d_in[12];
    const float* be     = (const float*)d_in[13];
    const float* We_a   = (const float*)d_in[14];
    const float* be_a   = (const float*)d_in[15];
    const float* Wg     = (const float*)d_in[16];
    const float* bg     = (const float*)d_in[17];
    const float* Wphi   = (const float*)d_in[18];
    const float* bphi   = (const float*)d_in[19];
    const float* Wpsi1  = (const float*)d_in[20];
    const float* bpsi1  = (const float*)d_in[21];
    const float* Wpsi2  = (const float*)d_in[22];
    const float* bpsi2  = (const float*)d_in[23];
    const float* Wres   = (const float*)d_in[24];
    const float* bres   = (const float*)d_in[25];
    const float* W1     = (const float*)d_in[26];
    const float* b1     = (const float*)d_in[27];
    const float* W2     = (const float*)d_in[28];
    const float* b2     = (const float*)d_in[29];
    const float* Wo     = (const float*)d_in[30];
    const float* bo     = (const float*)d_in[31];
    float* out = (float*)d_out;

    float* s = nullptr;
    cudaGetSymbolAddress((void**)&s, g_scratch);
    float* adapt  = s + OFF_ADAPT;
    float* am     = s + OFF_AM;
    float* part   = s + OFF_PART;
    float* gate   = s + OFF_GATE;
    float* Wdyn   = s + OFF_WDYN;
    float* bcat   = s + OFF_BCAT;
    float* mix    = s + OFF_MIX;
    float* resid  = s + OFF_RESID;
    float* hbuf   = s + OFF_H;
    float* kapart = s + OFF_KAPART;

    __nv_bfloat16* bb = (__nv_bfloat16*)(s + OFF_BF16);
    __nv_bfloat16 *xh = bb + BF_XH,   *xl = bb + BF_XL;
    __nv_bfloat16 *wfh = bb + BF_WFH, *wfl = bb + BF_WFL;
    __nv_bfloat16 *wdh = bb + BF_WDH, *wdl = bb + BF_WDL;
    __nv_bfloat16 *tph = bb + BF_TPH, *tpl = bb + BF_TPL;
    __nv_bfloat16 *wph = bb + BF_WPH, *wpl = bb + BF_WPL;
    __nv_bfloat16 *cth = bb + BF_CATH, *ctl = bb + BF_CATL;
    __nv_bfloat16 *wrh = bb + BF_WRH, *wrl = bb + BF_WRL;
    __nv_bfloat16 *w1h = bb + BF_W1H, *w1l = bb + BF_W1L;
    __nv_bfloat16 *cbh = bb + BF_CBH, *cbl = bb + BF_CBL;
    __nv_bfloat16 *woh = bb + BF_WOH, *wol = bb + BF_WOL;
    __nv_bfloat16 *wp1h = bb + BF_WP1H, *wp1l = bb + BF_WP1L;

    const int SM_FUSED = 100352;                       // fused_mix_ka
    const int SM_3C    = 3 * 65536 + 1024;             // 197632 fused_resid_h
    const int SM_6464  = 3 * (8192 + 8192) + 1024;     // 50176
    cudaFuncSetAttribute(gemm_hmma<64, 64, 0>, cudaFuncAttributeMaxDynamicSharedMemorySize, SM_6464);
    cudaFuncSetAttribute(ka2_moe_kernel, cudaFuncAttributeMaxDynamicSharedMemorySize, SM_6464);
    cudaFuncSetAttribute(fused_mix_ka,  cudaFuncAttributeMaxDynamicSharedMemorySize, SM_FUSED);
    cudaFuncSetAttribute(fused_resid_h, cudaFuncAttributeMaxDynamicSharedMemorySize, SM_3C);

    // 1. x split
    split_kernel<<<1024, 256>>>(x, xh, xl);
    // 2. W_feat + Wpsi2 tsplit + bcat + lf split into concat cols 768+
    prep2_kernel<<<3126, 256>>>(W_feat, wfh, wfl, Wpsi2, wph, wpl,
                                bt, bc, be, bcat, lf, cth, ctl);
    // 3. Wres + W1 + Wo + Wpsi1^T tsplit
    prep3_kernel<<<3808, 256>>>(Wres, wrh, wrl, W1, w1h, w1l, Wo, woh, wol,
                                Wpsi1, wp1h, wp1l);
    // 4. adapt GEMM  [4096,128]   <-- ncu window
    gemm_hmma<64, 64, 0><<<dim3(2, 64), 256, SM_6464>>>(xh, xl, wfh, wfl, b_feat, adapt, NTOK, ADIM, DDIM);
    // 5-6. am
    colsum_part_kernel<<<32, 128>>>(adapt, part);
    colsum_fin_kernel<<<1, 128>>>(part, am);
    // 7-8. dynamic weights + transpose-split
    dynw_kernel<<<384, 256>>>(Wt, Wt_a, bt_a, Wc, Wc_a, bc_a, We, We_a, be_a, am, Wdyn);
    tsplit_kernel<<<384, 256>>>(Wdyn, wdh, wdl, DDIM, DSUM);
    // 9. gate softmax
    gate_kernel<<<NTOK / 8, 256>>>(adapt, Wg, bg, gate);
    // 10. FUSED: mix GEMM (384; tok/chan tiles split directly into concat) + KA stage 1 (256)
    fused_mix_ka<<<640, 256, SM_FUSED>>>(xh, xl, wdh, wdl, bcat, mix, cth, ctl,
                                         x, Wphi, bphi, wp1h, wp1l, kapart);
    // 11. KA finish
    ka_finish_kernel<<<256, 256>>>(kapart, bpsi1, tph, tpl);
    // 12. ka2 GEMM + MoE epilogue -> concat cols 512..767
    ka2_moe_kernel<<<dim3(4, 64), 256, SM_6464>>>(tph, tpl, wph, wpl, bpsi2,
                                                  mix, gate, cth, ctl);
    // 13. FUSED: resid GEMM 3-combo (384) + h GEMM (64)
    fused_resid_h<<<448, 256, SM_3C>>>(cth, ctl, wrh, wrl, bres, resid,
                                       w1h, w1l, b1, hbuf);
    // 14. combine (reads bf16 concat, emits bf16 hi/lo)
    combine_kernel<<<NTOK / 8, 256>>>(hbuf, W2, b2, cth, ctl, resid, cbh, cbl);
    // 15. out = comb @ Wo + bo  [4096,256]
    gemm_hmma<64, 64, 0><<<dim3(4, 64), 256, SM_6464>>>(cbh, cbl, woh, wol, bo, out, NTOK, DDIM, DSUM);
}

// round 17
// speedup vs baseline: 1.0687x; 1.0687x over previous
#include <cuda_runtime.h>
#include <cuda_bf16.h>
#include <math.h>
#include <stdint.h>

// ---------------------------------------------------------------------------
// Problem constants
// ---------------------------------------------------------------------------
#define NTOK   4096      // B*S
#define DDIM   256
#define DLF    768
#define ADIM   128
#define DSUM   1536
#define HIDD   64

typedef unsigned long long ull;

// ---------------------------------------------------------------------------
// helpers
// ---------------------------------------------------------------------------
__device__ __forceinline__ float gelu_f(float v) {
    return 0.5f * v * (1.0f + erff(v * 0.70710678118654752440f));
}
__device__ __forceinline__ uint32_t smem_to_u32(const void* p) {
    uint32_t a;
    asm("{ .reg .u64 t; cvta.to.shared.u64 t, %1; cvt.u32.u64 %0, t; }" : "=r"(a) : "l"(p));
    return a;
}
#define SMEM_SWIZZLE_128B(o) ((o) ^ (((o) >> 3) & 0x70))

__device__ __forceinline__ void cp_async16(uint32_t saddr, const void* gptr) {
    asm volatile("cp.async.cg.shared.global [%0], [%1], 16;" :: "r"(saddr), "l"(gptr));
}
#define CP_COMMIT() asm volatile("cp.async.commit_group;" ::: "memory")
#define CP_WAIT1()  asm volatile("cp.async.wait_group 1;"  ::: "memory")
#define CP_WAIT0()  asm volatile("cp.async.wait_group 0;"  ::: "memory")

__device__ __forceinline__ void ldsm_x4(uint32_t addr, uint32_t& r0, uint32_t& r1,
                                        uint32_t& r2, uint32_t& r3) {
    asm volatile("ldmatrix.sync.aligned.m8n8.x4.shared.b16 {%0,%1,%2,%3}, [%4];"
                 : "=r"(r0), "=r"(r1), "=r"(r2), "=r"(r3) : "r"(addr));
}
__device__ __forceinline__ void ldsm_x2(uint32_t addr, uint32_t& r0, uint32_t& r1) {
    asm volatile("ldmatrix.sync.aligned.m8n8.x2.shared.b16 {%0,%1}, [%2];"
                 : "=r"(r0), "=r"(r1) : "r"(addr));
}
__device__ __forceinline__ void mma16816(float& c0, float& c1, float& c2, float& c3,
                                         uint32_t a0, uint32_t a1, uint32_t a2, uint32_t a3,
                                         uint32_t b0, uint32_t b1) {
    asm volatile("mma.sync.aligned.m16n8k16.row.col.f32.bf16.bf16.f32 "
                 "{%0,%1,%2,%3}, {%4,%5,%6,%7}, {%8,%9}, {%0,%1,%2,%3};"
                 : "+f"(c0), "+f"(c1), "+f"(c2), "+f"(c3)
                 : "r"(a0), "r"(a1), "r"(a2), "r"(a3), "r"(b0), "r"(b1));
}

__device__ __forceinline__ void split_store(float v, __nv_bfloat16* hi, __nv_bfloat16* lo) {
    __nv_bfloat16 h = __float2bfloat16(v);
    *hi = h;
    *lo = __float2bfloat16(v - __bfloat162float(h));
}

// ---------------------------------------------------------------------------
// Scratch (fp32 region then bf16 region)
// ---------------------------------------------------------------------------
#define OFF_ADAPT   0u
#define OFF_AM      524288u
#define OFF_PART    524416u
#define OFF_GATE    528512u
#define OFF_WDYN    548992u
#define OFF_BCAT    942208u
#define OFF_MIX     943744u
#define OFF_KA      7497344u
#define OFF_RESID   14837376u
#define OFF_H       21128832u
#define OFF_KAPART  27682432u          // 4 slices x 4096 x 64
#define OFF_BF16    28731008u          // start of bf16 region (float units)

// bf16 offsets (in bf16 elements from bf16 base)
#define BF_XH    0u
#define BF_XL    1048576u
#define BF_WFH   2097152u
#define BF_WFL   2129920u
#define BF_WDH   2162688u
#define BF_WDL   2555904u
#define BF_TPH   2949120u
#define BF_TPL   3211264u
#define BF_WPH   3473408u
#define BF_WPL   3489792u
#define BF_CATH  3506176u
#define BF_CATL  9797632u
#define BF_WRH   16089088u
#define BF_WRL   18448384u
#define BF_W1H   20807680u
#define BF_W1L   20905984u
#define BF_CBH   21004288u
#define BF_CBL   27295744u
#define BF_WOH   33587200u
#define BF_WOL   33980416u
#define BF_WP1H  34373632u             // Wpsi1^T hi [64][16384]
#define BF_WP1L  35422208u

#define SCRATCH_FLOATS (28731008u + 18235392u)
__device__ float g_scratch[SCRATCH_FLOATS];

// ---------------------------------------------------------------------------
// split: fp32 [n] -> bf16 hi, lo
// ---------------------------------------------------------------------------
__global__ void split_kernel(const float* __restrict__ src,
                             __nv_bfloat16* __restrict__ hi,
                             __nv_bfloat16* __restrict__ lo)
{
    const int i = blockIdx.x * 256 + threadIdx.x;
    float4 v = ((const float4*)src)[i];
    __nv_bfloat16 hx = __float2bfloat16(v.x), hy = __float2bfloat16(v.y);
    __nv_bfloat16 hz = __float2bfloat16(v.z), hw = __float2bfloat16(v.w);
    __nv_bfloat162* hp = (__nv_bfloat162*)hi;
    __nv_bfloat162* lp = (__nv_bfloat162*)lo;
    hp[2*i]   = __nv_bfloat162(hx, hy);
    hp[2*i+1] = __nv_bfloat162(hz, hw);
    lp[2*i]   = __nv_bfloat162(__float2bfloat16(v.x - __bfloat162float(hx)),
                               __float2bfloat16(v.y - __bfloat162float(hy)));
    lp[2*i+1] = __nv_bfloat162(__float2bfloat16(v.z - __bfloat162float(hz)),
                               __float2bfloat16(v.w - __bfloat162float(hw)));
}

// ---------------------------------------------------------------------------
// transpose+split body (flat 256 threads): W [K,N] fp32 -> th, tl [N,K] bf16
// ---------------------------------------------------------------------------
__device__ __forceinline__ void
tsplit_body(const float* __restrict__ W, __nv_bfloat16* __restrict__ th,
            __nv_bfloat16* __restrict__ tl, int K, int N, int bid)
{
    __shared__ float t[32][33];
    const int nb = (bid % (N / 32)) * 32;
    const int kb = (bid / (N / 32)) * 32;
    const int tx = threadIdx.x & 31, ty = threadIdx.x >> 5;
#pragma unroll
    for (int j = 0; j < 32; j += 8)
        t[ty + j][tx] = W[(size_t)(kb + ty + j) * N + nb + tx];
    __syncthreads();
#pragma unroll
    for (int j = 0; j < 32; j += 8) {
        float v = t[tx][ty + j];
        __nv_bfloat16 h = __float2bfloat16(v);
        th[(size_t)(nb + ty + j) * K + kb + tx] = h;
        tl[(size_t)(nb + ty + j) * K + kb + tx] = __float2bfloat16(v - __bfloat162float(h));
    }
}

__global__ void tsplit_kernel(const float* __restrict__ W,
                              __nv_bfloat16* __restrict__ th,
                              __nv_bfloat16* __restrict__ tl,
                              int K, int N)
{
    tsplit_body(W, th, tl, K, N, blockIdx.x);
}

// prep2: Wfeat tsplit (32 blocks) + Wpsi2 tsplit (16) + bcat (6)
__global__ void prep2_kernel(const float* __restrict__ W_feat,
                             __nv_bfloat16* __restrict__ wfh, __nv_bfloat16* __restrict__ wfl,
                             const float* __restrict__ Wpsi2,
                             __nv_bfloat16* __restrict__ wph, __nv_bfloat16* __restrict__ wpl,
                             const float* __restrict__ bt, const float* __restrict__ bc,
                             const float* __restrict__ be, float* __restrict__ bcat)
{
    const int bid = blockIdx.x;
    if (bid < 32) {
        tsplit_body(W_feat, wfh, wfl, DDIM, ADIM, bid);
    } else if (bid < 48) {
        tsplit_body(Wpsi2, wph, wpl, HIDD, DDIM, bid - 32);
    } else {
        int c = (bid - 48) * 256 + threadIdx.x;
        if (c < DSUM) {
            if (c < 256)      bcat[c] = bt[c];
            else if (c < 512) bcat[c] = bc[c - 256];
            else              bcat[c] = be[c - 512];
        }
    }
}

// prep3: Wres (2304) + W1 (96) + Wo (384) + Wpsi1^T (1024) tsplits
__global__ void prep3_kernel(const float* __restrict__ Wres,
                             __nv_bfloat16* __restrict__ wrh, __nv_bfloat16* __restrict__ wrl,
                             const float* __restrict__ W1,
                             __nv_bfloat16* __restrict__ w1h, __nv_bfloat16* __restrict__ w1l,
                             const float* __restrict__ Wo,
                             __nv_bfloat16* __restrict__ woh, __nv_bfloat16* __restrict__ wol,
                             const float* __restrict__ Wpsi1,
                             __nv_bfloat16* __restrict__ wp1h, __nv_bfloat16* __restrict__ wp1l)
{
    const int bid = blockIdx.x;
    if (bid < 2304)      tsplit_body(Wres, wrh, wrl, DSUM, DSUM, bid);
    else if (bid < 2400) tsplit_body(W1, w1h, w1l, DSUM, HIDD, bid - 2304);
    else if (bid < 2784) tsplit_body(Wo, woh, wol, DSUM, DDIM, bid - 2400);
    else                 tsplit_body(Wpsi1, wp1h, wp1l, 16384, HIDD, bid - 2784);
}

// ---------------------------------------------------------------------------
// gemm_body: HMMA bf16 3-split, chunk-major over the 3 split blocks
// (3-stage ring). Still used by the mix GEMM (smem-constrained when fused).
// ---------------------------------------------------------------------------
template <int BM, int BN, bool GELU>
__device__ __forceinline__ void
gemm_body(const __nv_bfloat16* __restrict__ Ahi, const __nv_bfloat16* __restrict__ Alo,
          const __nv_bfloat16* __restrict__ BThi, const __nv_bfloat16* __restrict__ BTlo,
          const float* __restrict__ bias, float* __restrict__ C,
          int M, int N, int K, int bm, int bn, char* smem_raw)
{
    constexpr int ASZ = BM * 128;
    constexpr int BSZ = BN * 128;
    constexpr int STG = ASZ + BSZ;
    constexpr int WM  = BM / 64;
    constexpr int WN  = 8 / WM;
    constexpr int WTN = BN / WN;
    constexpr int NF  = WTN / 8;

    const uint32_t tile0 = (smem_to_u32(smem_raw) + 1023) & ~1023u;

    const int tid = threadIdx.x;
    const int wid = tid >> 5, lane = tid & 31;
    const int wm = (WM == 1) ? 0 : (wid & 1);
    const int wn = (WM == 1) ? wid : (wid >> 1);
    const int KC = K >> 6;
    const int NC = 3 * KC;

    float acc[4][NF][4];
#pragma unroll
    for (int mf = 0; mf < 4; mf++)
#pragma unroll
        for (int nf = 0; nf < NF; nf++)
#pragma unroll
            for (int i = 0; i < 4; i++) acc[mf][nf][i] = 0.f;

    auto stage = [&](int c) {
        const int buf = c % 3;
        const int blk = c / KC;
        const int k0  = (c - blk * KC) << 6;
        const __nv_bfloat16* Asrc = ((blk < 2) ? Ahi : Alo) + (size_t)bm * K + k0;
        const __nv_bfloat16* Bsrc = ((blk == 1) ? BTlo : BThi) + (size_t)bn * K + k0;
        const uint32_t ab = tile0 + buf * STG;
        const uint32_t bb = ab + ASZ;
#pragma unroll
        for (int i = 0; i < BM / 32; i++) {
            int u = i * 256 + tid;
            int row = u >> 3, seg = u & 7;
            uint32_t off = row * 128 + seg * 16;
            cp_async16(ab + SMEM_SWIZZLE_128B(off), Asrc + (size_t)row * K + seg * 8);
        }
#pragma unroll
        for (int i = 0; i < BN / 32; i++) {
            int u = i * 256 + tid;
            int row = u >> 3, seg = u & 7;
            uint32_t off = row * 128 + seg * 16;
            cp_async16(bb + SMEM_SWIZZLE_128B(off), Bsrc + (size_t)row * K + seg * 8);
        }
    };

    auto compute = [&](int buf) {
        const uint32_t ab = tile0 + buf * STG;
        const uint32_t bb = ab + ASZ;
#pragma unroll
        for (int k16 = 0; k16 < 4; k16++) {
            uint32_t ar[4][4];
#pragma unroll
            for (int mf = 0; mf < 4; mf++) {
                int row = wm * 64 + mf * 16 + (lane & 15);
                uint32_t off = row * 128 + k16 * 32 + ((lane >> 4) << 4);
                ldsm_x4(ab + SMEM_SWIZZLE_128B(off), ar[mf][0], ar[mf][1], ar[mf][2], ar[mf][3]);
            }
            uint32_t br[NF][2];
            if (NF == 1) {
                int n = wn * WTN + (lane & 7);
                uint32_t off = n * 128 + k16 * 32 + (((lane >> 3) & 1) << 4);
                ldsm_x2(bb + SMEM_SWIZZLE_128B(off), br[0][0], br[0][1]);
            } else {
#pragma unroll
                for (int nb = 0; nb < NF / 2; nb++) {
                    int grp = lane >> 3;
                    int n = wn * WTN + nb * 16 + ((grp >> 1) << 3) + (lane & 7);
                    uint32_t off = n * 128 + k16 * 32 + ((grp & 1) << 4);
                    ldsm_x4(bb + SMEM_SWIZZLE_128B(off),
                            br[2*nb][0], br[2*nb][1], br[2*nb+1][0], br[2*nb+1][1]);
                }
            }
#pragma unroll
            for (int mf = 0; mf < 4; mf++)
#pragma unroll
                for (int nf = 0; nf < NF; nf++)
                    mma16816(acc[mf][nf][0], acc[mf][nf][1], acc[mf][nf][2], acc[mf][nf][3],
                             ar[mf][0], ar[mf][1], ar[mf][2], ar[mf][3],
                             br[nf][0], br[nf][1]);
        }
    };

    stage(0); CP_COMMIT();
    if (NC > 1) { stage(1); CP_COMMIT(); }
    for (int c = 0; c < NC; c++) {
        if (c + 1 < NC) CP_WAIT1(); else CP_WAIT0();
        __syncthreads();
        if (c + 2 < NC) { stage(c + 2); CP_COMMIT(); }
        compute(c % 3);
    }

#pragma unroll
    for (int nf = 0; nf < NF; nf++) {
        int col = bn + wn * WTN + nf * 8 + ((lane & 3) << 1);
        float2 bv = *(const float2*)(bias + col);
#pragma unroll
        for (int mf = 0; mf < 4; mf++) {
            int row = bm + wm * 64 + mf * 16 + (lane >> 2);
            float x0 = acc[mf][nf][0] + bv.x;
            float x1 = acc[mf][nf][1] + bv.y;
            float x2 = acc[mf][nf][2] + bv.x;
            float x3 = acc[mf][nf][3] + bv.y;
            if (GELU) { x0 = gelu_f(x0); x1 = gelu_f(x1); x2 = gelu_f(x2); x3 = gelu_f(x3); }
            *(float2*)&C[(size_t)row * N + col]       = make_float2(x0, x1);
            *(float2*)&C[(size_t)(row + 8) * N + col] = make_float2(x2, x3);
        }
    }
}

// ---------------------------------------------------------------------------
// gemm3cb_body: stage-once / 3-combo GEMM, generalized BM/BN, 3-stage ring,
// single __syncthreads per chunk. Stage = [Ah | Al | Bh | Bl].
// ---------------------------------------------------------------------------
template <int BM, int BN, bool GELU>
__device__ __forceinline__ void
gemm3cb_body(const __nv_bfloat16* __restrict__ Ahi, const __nv_bfloat16* __restrict__ Alo,
             const __nv_bfloat16* __restrict__ BThi, const __nv_bfloat16* __restrict__ BTlo,
             const float* __restrict__ bias, float* __restrict__ C,
             int N, int K, int bm, int bn, char* smem_raw)
{
    constexpr int TA  = BM * 128;
    constexpr int TB  = BN * 128;
    constexpr int STG = 2 * TA + 2 * TB;
    constexpr int WM  = BM / 64;
    constexpr int WN  = 8 / WM;
    constexpr int WTN = BN / WN;
    constexpr int NF  = WTN / 8;

    const uint32_t tile0 = (smem_to_u32(smem_raw) + 1023) & ~1023u;

    const int tid = threadIdx.x;
    const int wid = tid >> 5, lane = tid & 31;
    const int wm = (WM == 1) ? 0 : (wid & 1);
    const int wn = (WM == 1) ? wid : (wid >> 1);
    const int NC = K >> 6;

    float acc[4][NF][4];
#pragma unroll
    for (int mf = 0; mf < 4; mf++)
#pragma unroll
        for (int nf = 0; nf < NF; nf++)
#pragma unroll
            for (int i = 0; i < 4; i++) acc[mf][nf][i] = 0.f;

    auto stage = [&](int c) {
        const int k0 = c << 6;
        const uint32_t sb = tile0 + (c % 3) * STG;
        const __nv_bfloat16* Ah = Ahi + (size_t)bm * K + k0;
        const __nv_bfloat16* Al = Alo + (size_t)bm * K + k0;
        const __nv_bfloat16* Bh = BThi + (size_t)bn * K + k0;
        const __nv_bfloat16* Bl = BTlo + (size_t)bn * K + k0;
#pragma unroll
        for (int i = 0; i < BM / 32; i++) {
            int u = i * 256 + tid;
            int row = u >> 3, seg = u & 7;
            uint32_t off = SMEM_SWIZZLE_128B((uint32_t)(row * 128 + seg * 16));
            cp_async16(sb + off,      Ah + (size_t)row * K + seg * 8);
            cp_async16(sb + TA + off, Al + (size_t)row * K + seg * 8);
        }
#pragma unroll
        for (int i = 0; i < BN / 32; i++) {
            int u = i * 256 + tid;
            int row = u >> 3, seg = u & 7;
            uint32_t off = SMEM_SWIZZLE_128B((uint32_t)(row * 128 + seg * 16));
            cp_async16(sb + 2 * TA + off,      Bh + (size_t)row * K + seg * 8);
            cp_async16(sb + 2 * TA + TB + off, Bl + (size_t)row * K + seg * 8);
        }
    };

    auto compute = [&](int buf) {
        const uint32_t ah = tile0 + buf * STG;
        const uint32_t al = ah + TA;
        const uint32_t bh = ah + 2 * TA;
        const uint32_t bl = bh + TB;
#pragma unroll
        for (int k16 = 0; k16 < 4; k16++) {
            uint32_t Ahf[4][4], Alf[4][4], Bhf[NF][2], Blf[NF][2];
#pragma unroll
            for (int mf = 0; mf < 4; mf++) {
                int row = wm * 64 + mf * 16 + (lane & 15);
                uint32_t off = SMEM_SWIZZLE_128B(
                    (uint32_t)(row * 128 + k16 * 32 + ((lane >> 4) << 4)));
                ldsm_x4(ah + off, Ahf[mf][0], Ahf[mf][1], Ahf[mf][2], Ahf[mf][3]);
                ldsm_x4(al + off, Alf[mf][0], Alf[mf][1], Alf[mf][2], Alf[mf][3]);
            }
            if (NF == 1) {
                int n = wn * WTN + (lane & 7);
                uint32_t off = SMEM_SWIZZLE_128B(
                    (uint32_t)(n * 128 + k16 * 32 + (((lane >> 3) & 1) << 4)));
                ldsm_x2(bh + off, Bhf[0][0], Bhf[0][1]);
                ldsm_x2(bl + off, Blf[0][0], Blf[0][1]);
            } else {
#pragma unroll
                for (int nb = 0; nb < NF / 2; nb++) {
                    int grp = lane >> 3;
                    int n = wn * WTN + nb * 16 + ((grp >> 1) << 3) + (lane & 7);
                    uint32_t off = SMEM_SWIZZLE_128B(
                        (uint32_t)(n * 128 + k16 * 32 + ((grp & 1) << 4)));
                    ldsm_x4(bh + off, Bhf[2*nb][0], Bhf[2*nb][1], Bhf[2*nb+1][0], Bhf[2*nb+1][1]);
                    ldsm_x4(bl + off, Blf[2*nb][0], Blf[2*nb][1], Blf[2*nb+1][0], Blf[2*nb+1][1]);
                }
            }
            // combo 1: Ah x Bh
#pragma unroll
            for (int mf = 0; mf < 4; mf++)
#pragma unroll
                for (int nf = 0; nf < NF; nf++)
                    mma16816(acc[mf][nf][0], acc[mf][nf][1], acc[mf][nf][2], acc[mf][nf][3],
                             Ahf[mf][0], Ahf[mf][1], Ahf[mf][2], Ahf[mf][3],
                             Bhf[nf][0], Bhf[nf][1]);
            // combo 2: Ah x Bl
#pragma unroll
            for (int mf = 0; mf < 4; mf++)
#pragma unroll
                for (int nf = 0; nf < NF; nf++)
                    mma16816(acc[mf][nf][0], acc[mf][nf][1], acc[mf][nf][2], acc[mf][nf][3],
                             Ahf[mf][0], Ahf[mf][1], Ahf[mf][2], Ahf[mf][3],
                             Blf[nf][0], Blf[nf][1]);
            // combo 3: Al x Bh
#pragma unroll
            for (int mf = 0; mf < 4; mf++)
#pragma unroll
                for (int nf = 0; nf < NF; nf++)
                    mma16816(acc[mf][nf][0], acc[mf][nf][1], acc[mf][nf][2], acc[mf][nf][3],
                             Alf[mf][0], Alf[mf][1], Alf[mf][2], Alf[mf][3],
                             Bhf[nf][0], Bhf[nf][1]);
        }
    };

    stage(0); CP_COMMIT();
    if (NC > 1) { stage(1); CP_COMMIT(); }
    for (int c = 0; c < NC; c++) {
        if (c + 1 < NC) CP_WAIT1(); else CP_WAIT0();
        __syncthreads();
        if (c + 2 < NC) { stage(c + 2); CP_COMMIT(); }
        compute(c % 3);
    }

#pragma unroll
    for (int nf = 0; nf < NF; nf++) {
        int col = bn + wn * WTN + nf * 8 + ((lane & 3) << 1);
        float2 bv = *(const float2*)(bias + col);
#pragma unroll
        for (int mf = 0; mf < 4; mf++) {
            int row = bm + wm * 64 + mf * 16 + (lane >> 2);
            float x0 = acc[mf][nf][0] + bv.x;
            float x1 = acc[mf][nf][1] + bv.y;
            float x2 = acc[mf][nf][2] + bv.x;
            float x3 = acc[mf][nf][3] + bv.y;
            if (GELU) { x0 = gelu_f(x0); x1 = gelu_f(x1); x2 = gelu_f(x2); x3 = gelu_f(x3); }
            *(float2*)&C[(size_t)row * N + col]       = make_float2(x0, x1);
            *(float2*)&C[(size_t)(row + 8) * N + col] = make_float2(x2, x3);
        }
    }
}

// standalone 3-combo GEMM kernel (64x64 tiles, 2 CTAs/SM)
template <bool GELU>
__global__ void __launch_bounds__(256, 2)
gemm3c_hmma(const __nv_bfloat16* __restrict__ Ahi, const __nv_bfloat16* __restrict__ Alo,
            const __nv_bfloat16* __restrict__ BThi, const __nv_bfloat16* __restrict__ BTlo,
            const float* __restrict__ bias, float* __restrict__ C,
            int M, int N, int K)
{
    extern __shared__ char smem_raw[];
    gemm3cb_body<64, 64, GELU>(Ahi, Alo, BThi, BTlo, bias, C, N, K,
                               blockIdx.y * 64, blockIdx.x * 64, smem_raw);
}

// ---------------------------------------------------------------------------
// KA stage-1, HMMA version.
// ---------------------------------------------------------------------------
__device__ __forceinline__ void
ka_hmma_body(const float* __restrict__ xf, const float* __restrict__ Wphi,
             const float* __restrict__ bphi,
             const __nv_bfloat16* __restrict__ wp1h, const __nv_bfloat16* __restrict__ wp1l,
             float* __restrict__ kapart, int b, char* smem_raw)
{
    const uint32_t base = smem_to_u32(smem_raw);
    const uint32_t tile0 = (base + 1023) & ~1023u;
    char* cbase = smem_raw + (tile0 - base);

    const uint32_t PH = 32768, PL = 40960;
    float* xs  = (float*)(cbase + 49152);
    float* wps = (float*)(cbase + 65792);
    float* bps = (float*)(cbase + 82176);

    const int tid = threadIdx.x;
    const int s   = b & 3;
    const int t0  = (b >> 2) << 6;

    {
        int tok = tid >> 2, dq = (tid & 3) << 4;
        const float* xp = xf + (size_t)(t0 + tok) * 256 + (s << 6) + dq;
#pragma unroll
        for (int j = 0; j < 16; j += 4) {
            float4 v = *(const float4*)(xp + j);
            xs[(dq + j + 0) * 65 + tok] = v.x;
            xs[(dq + j + 1) * 65 + tok] = v.y;
            xs[(dq + j + 2) * 65 + tok] = v.z;
            xs[(dq + j + 3) * 65 + tok] = v.w;
        }
        const float4* wsrc = (const float4*)(Wphi + (s << 12));
        const float4* bsrc = (const float4*)(bphi + (s << 12));
        float4* wdst = (float4*)wps;
        float4* bdst = (float4*)bps;
#pragma unroll
        for (int r = 0; r < 4; r++) {
            wdst[tid + (r << 8)] = wsrc[tid + (r << 8)];
            bdst[tid + (r << 8)] = bsrc[tid + (r << 8)];
        }
    }

    auto stageB = [&](int d) {
        const uint32_t dsth = tile0 + (d & 1) * 16384;
        const uint32_t dstl = dsth + 8192;
        const __nv_bfloat16* sh = wp1h + (s << 12) + (d << 6);
        const __nv_bfloat16* sl = wp1l + (s << 12) + (d << 6);
#pragma unroll
        for (int i = 0; i < 2; i++) {
            int u = i * 256 + tid;
            int row = u >> 3, seg = u & 7;
            uint32_t off = SMEM_SWIZZLE_128B((uint32_t)(row * 128 + seg * 16));
            cp_async16(dsth + off, sh + (size_t)row * 16384 + seg * 8);
            cp_async16(dstl + off, sl + (size_t)row * 16384 + seg * 8);
        }
    };

    stageB(0); CP_COMMIT();
    __syncthreads();

    const int wid = tid >> 5, lane = tid & 31;
    const int wm = wid & 1, wn = wid >> 1;
    const int ptok = tid & 63, hq = tid >> 6;

    float acc[2][2][4];
#pragma unroll
    for (int mf = 0; mf < 2; mf++)
#pragma unroll
        for (int nf = 0; nf < 2; nf++)
#pragma unroll
            for (int i = 0; i < 4; i++) acc[mf][nf][i] = 0.f;

    for (int d = 0; d < 64; d++) {
        if (d + 1 < 64) { stageB(d + 1); CP_COMMIT(); }
        {
            float xv = xs[d * 65 + ptok];
            const float* wr = wps + (d << 6);
            const float* br2 = bps + (d << 6);
#pragma unroll
            for (int j = 0; j < 16; j += 2) {
                int h = (hq << 4) + j;
                float v0 = gelu_f(fmaf(xv, wr[h],     br2[h]));
                float v1 = gelu_f(fmaf(xv, wr[h + 1], br2[h + 1]));
                __nv_bfloat16 h0 = __float2bfloat16(v0);
                __nv_bfloat16 h1 = __float2bfloat16(v1);
                __nv_bfloat162 hp(h0, h1);
                __nv_bfloat162 lp(__float2bfloat16(v0 - __bfloat162float(h0)),
                                  __float2bfloat16(v1 - __bfloat162float(h1)));
                uint32_t off = SMEM_SWIZZLE_128B((uint32_t)(ptok * 128 + h * 2));
                *(__nv_bfloat162*)(cbase + PH + off) = hp;
                *(__nv_bfloat162*)(cbase + PL + off) = lp;
            }
        }
        if (d + 1 < 64) CP_WAIT1(); else CP_WAIT0();
        __syncthreads();
        {
            const uint32_t bh = tile0 + (d & 1) * 16384;
            const uint32_t bl = bh + 8192;
            const uint32_t ah = tile0 + PH, al = tile0 + PL;
#pragma unroll
            for (int k16 = 0; k16 < 4; k16++) {
                uint32_t Ah[2][4], Al[2][4], Bh[2][2], Bl[2][2];
#pragma unroll
                for (int mf = 0; mf < 2; mf++) {
                    int row = wm * 32 + mf * 16 + (lane & 15);
                    uint32_t off = SMEM_SWIZZLE_128B(
                        (uint32_t)(row * 128 + k16 * 32 + ((lane >> 4) << 4)));
                    ldsm_x4(ah + off, Ah[mf][0], Ah[mf][1], Ah[mf][2], Ah[mf][3]);
                    ldsm_x4(al + off, Al[mf][0], Al[mf][1], Al[mf][2], Al[mf][3]);
                }
                {
                    int grp = lane >> 3;
                    int n = wn * 16 + ((grp >> 1) << 3) + (lane & 7);
                    uint32_t off = SMEM_SWIZZLE_128B(
                        (uint32_t)(n * 128 + k16 * 32 + ((grp & 1) << 4)));
                    ldsm_x4(bh + off, Bh[0][0], Bh[0][1], Bh[1][0], Bh[1][1]);
                    ldsm_x4(bl + off, Bl[0][0], Bl[0][1], Bl[1][0], Bl[1][1]);
                }
#pragma unroll
                for (int mf = 0; mf < 2; mf++)
#pragma unroll
                    for (int nf = 0; nf < 2; nf++) {
                        mma16816(acc[mf][nf][0], acc[mf][nf][1], acc[mf][nf][2], acc[mf][nf][3],
                                 Ah[mf][0], Ah[mf][1], Ah[mf][2], Ah[mf][3],
                                 Bh[nf][0], Bh[nf][1]);
                        mma16816(acc[mf][nf][0], acc[mf][nf][1], acc[mf][nf][2], acc[mf][nf][3],
                                 Al[mf][0], Al[mf][1], Al[mf][2], Al[mf][3],
                                 Bh[nf][0], Bh[nf][1]);
                        mma16816(acc[mf][nf][0], acc[mf][nf][1], acc[mf][nf][2], acc[mf][nf][3],
                                 Ah[mf][0], Ah[mf][1], Ah[mf][2], Ah[mf][3],
                                 Bl[nf][0], Bl[nf][1]);
                    }
            }
        }
        __syncthreads();
    }

    float* pout = kapart + (size_t)s * (NTOK * HIDD) + (size_t)t0 * HIDD;
#pragma unroll
    for (int mf = 0; mf < 2; mf++)
#pragma unroll
        for (int nf = 0; nf < 2; nf++) {
            int row = wm * 32 + mf * 16 + (lane >> 2);
            int col = wn * 16 + nf * 8 + ((lane & 3) << 1);
            *(float2*)&pout[(size_t)row * HIDD + col] =
                make_float2(acc[mf][nf][0], acc[mf][nf][1]);
            *(float2*)&pout[(size_t)(row + 8) * HIDD + col] =
                make_float2(acc[mf][nf][2], acc[mf][nf][3]);
        }
}

// ---------------------------------------------------------------------------
// Fused kernels
// ---------------------------------------------------------------------------
__global__ void __launch_bounds__(256, 2)
fused_mix_ka(const __nv_bfloat16* __restrict__ xh, const __nv_bfloat16* __restrict__ xl,
             const __nv_bfloat16* __restrict__ wdh, const __nv_bfloat16* __restrict__ wdl,
             const float* __restrict__ bcat, float* __restrict__ mix,
             const float* __restrict__ xf, const float* __restrict__ Wphi,
             const float* __restrict__ bphi,
             const __nv_bfloat16* __restrict__ wp1h, const __nv_bfloat16* __restrict__ wp1l,
             float* __restrict__ kapart)
{
    extern __shared__ char smem_raw[];
    const int bid = blockIdx.x;
    if (bid < 384) {
        gemm_body<128, 128, false>(xh, xl, wdh, wdl, bcat, mix,
                                   NTOK, DSUM, DDIM,
                                   (bid / 12) * 128, (bid % 12) * 128, smem_raw);
    } else {
        ka_hmma_body(xf, Wphi, bphi, wp1h, wp1l, kapart, bid - 384, smem_raw);
    }
}

// resid via stage-once/3-combo 3-stage ring (384 blocks) + h GEMM 3c (64 blocks)
__global__ void __launch_bounds__(256)
fused_resid_h(const __nv_bfloat16* __restrict__ cth, const __nv_bfloat16* __restrict__ ctl,
              const __nv_bfloat16* __restrict__ wrh, const __nv_bfloat16* __restrict__ wrl,
              const float* __restrict__ bres, float* __restrict__ resid,
              const __nv_bfloat16* __restrict__ w1h, const __nv_bfloat16* __restrict__ w1l,
              const float* __restrict__ b1, float* __restrict__ hbuf)
{
    extern __shared__ char smem_raw[];
    const int bid = blockIdx.x;
    if (bid < 384) {
        gemm3cb_body<128, 128, false>(cth, ctl, wrh, wrl, bres, resid,
                                      DSUM, DSUM,
                                      (bid / 12) * 128, (bid % 12) * 128, smem_raw);
    } else {
        gemm3cb_body<64, 64, true>(cth, ctl, w1h, w1l, b1, hbuf,
                                   HIDD, DSUM, (bid - 384) * 64, 0, smem_raw);
    }
}

// ---------------------------------------------------------------------------
// am = mean over tokens of adapt
// ---------------------------------------------------------------------------
__global__ void colsum_part_kernel(const float* __restrict__ adapt, float* __restrict__ part)
{
    const int j = threadIdx.x;
    const int b = blockIdx.x;
    float s = 0.f;
#pragma unroll 8
    for (int r = 0; r < 128; r++) s += adapt[(size_t)(b * 128 + r) * ADIM + j];
    part[b * ADIM + j] = s;
}
__global__ void colsum_fin_kernel(const float* __restrict__ part, float* __restrict__ am)
{
    const int j = threadIdx.x;
    float s = 0.f;
#pragma unroll
    for (int b = 0; b < 32; b++) s += part[b * ADIM + j];
    am[j] = s * (1.0f / (float)NTOK);
}

// ---------------------------------------------------------------------------
// Dynamic weights
// ---------------------------------------------------------------------------
__global__ void dynw_kernel(const float* __restrict__ Wt,  const float* __restrict__ Wt_a, const float* __restrict__ bt_a,
                            const float* __restrict__ Wc,  const float* __restrict__ Wc_a, const float* __restrict__ bc_a,
                            const float* __restrict__ We,  const float* __restrict__ We_a, const float* __restrict__ be_a,
                            const float* __restrict__ am,  float* __restrict__ Wdyn)
{
    __shared__ float ams[ADIM];
    const int tid = threadIdx.x;
    if (tid < ADIM) ams[tid] = am[tid];
    __syncthreads();

    const int idx4 = blockIdx.x * 256 + tid;
    const int k    = idx4 / 384;
    const int c4   = (idx4 - k * 384) * 4;

    const float *Wa, *ba, *base;
    int m;
    if (c4 < 256)      { m = k * 256 + c4;          base = Wt; Wa = Wt_a; ba = bt_a; }
    else if (c4 < 512) { m = k * 256 + (c4 - 256);  base = Wc; Wa = Wc_a; ba = bc_a; }
    else {
        int e  = (c4 - 512) >> 8;
        int jj = (c4 - 512) & 255;
        m = k * 256 + jj;
        base = We + e * 65536;
        Wa   = We_a + (size_t)e * 8388608u;
        ba   = be_a + e * 65536;
    }
    float4 acc = *(const float4*)(base + m);
    float4 b4  = *(const float4*)(ba + m);
    acc.x += b4.x; acc.y += b4.y; acc.z += b4.z; acc.w += b4.w;
#pragma unroll 4
    for (int a = 0; a < ADIM; a++) {
        float s = ams[a];
        float4 w = *(const float4*)(Wa + (size_t)a * 65536 + m);
        acc.x = fmaf(s, w.x, acc.x);
        acc.y = fmaf(s, w.y, acc.y);
        acc.z = fmaf(s, w.z, acc.z);
        acc.w = fmaf(s, w.w, acc.w);
    }
    *(float4*)(Wdyn + (size_t)idx4 * 4) = acc;
}

// ---------------------------------------------------------------------------
// gate = softmax(adapt @ Wg + bg)
// ---------------------------------------------------------------------------
__global__ void gate_kernel(const float* __restrict__ adapt, const float* __restrict__ Wg,
                            const float* __restrict__ bg, float* __restrict__ gate)
{
    __shared__ float wgs[ADIM * 5];
    __shared__ float bgs[5];
    const int tid = threadIdx.x;
    for (int i = tid; i < ADIM * 5; i += 256) wgs[i] = Wg[i];
    if (tid < 5) bgs[tid] = bg[tid];
    __syncthreads();

    const int warp = tid >> 5, lane = tid & 31;
    const int n = (blockIdx.x << 3) + warp;

    float4 a4 = *(const float4*)(adapt + (size_t)n * ADIM + lane * 4);
    float av[4] = { a4.x, a4.y, a4.z, a4.w };
    float l[5] = { 0, 0, 0, 0, 0 };
#pragma unroll
    for (int q = 0; q < 4; q++) {
        int a = lane * 4 + q;
#pragma unroll
        for (int j = 0; j < 5; j++) l[j] = fmaf(av[q], wgs[a * 5 + j], l[j]);
    }
#pragma unroll
    for (int off = 16; off; off >>= 1)
#pragma unroll
        for (int j = 0; j < 5; j++) l[j] += __shfl_xor_sync(0xffffffffu, l[j], off);

    if (lane == 0) {
#pragma unroll
        for (int j = 0; j < 5; j++) l[j] += bgs[j];
        float mx = fmaxf(fmaxf(fmaxf(l[0], l[1]), fmaxf(l[2], l[3])), l[4]);
        float s = 0.f;
#pragma unroll
        for (int j = 0; j < 5; j++) { l[j] = __expf(l[j] - mx); s += l[j]; }
        float inv = 1.0f / s;
#pragma unroll
        for (int j = 0; j < 5; j++) gate[n * 5 + j] = l[j] * inv;
    }
}

// tpsi = gelu(sum of 4 partials + bpsi1) -> bf16 hi/lo
__global__ void ka_finish_kernel(const float* __restrict__ part,
                                 const float* __restrict__ bpsi1,
                                 __nv_bfloat16* __restrict__ tph,
                                 __nv_bfloat16* __restrict__ tpl)
{
    const int idx = blockIdx.x * 256 + threadIdx.x;
    const int jq = idx & 15;
    const float4* p = (const float4*)part;
    float4 a = p[idx];
    float4 b = p[65536 + idx];
    float4 c = p[131072 + idx];
    float4 d = p[196608 + idx];
    float4 bb = ((const float4*)bpsi1)[jq];
    float o[4];
    o[0] = gelu_f(a.x + b.x + c.x + d.x + bb.x);
    o[1] = gelu_f(a.y + b.y + c.y + d.y + bb.y);
    o[2] = gelu_f(a.z + b.z + c.z + d.z + bb.z);
    o[3] = gelu_f(a.w + b.w + c.w + d.w + bb.w);
#pragma unroll
    for (int q = 0; q < 4; q++) split_store(o[q], tph + idx * 4 + q, tpl + idx * 4 + q);
}

// ---------------------------------------------------------------------------
// concat[n] = [tok, chan, moe, lf]; emits ONLY bf16 hi/lo
// ---------------------------------------------------------------------------
__global__ void concat_kernel(const float* __restrict__ mix, const float* __restrict__ gate,
                              const float* __restrict__ ka, const float* __restrict__ lf,
                              __nv_bfloat16* __restrict__ cth, __nv_bfloat16* __restrict__ ctl)
{
    const int n = blockIdx.x;
    const int t = threadIdx.x;
    __shared__ float g[5];
    if (t < 5) g[t] = gate[n * 5 + t];
    __syncthreads();

    const float4* mx = (const float4*)(mix + (size_t)n * DSUM);
    float4 out;
    if (t < 128) {
        out = mx[t];
    } else if (t < 192) {
        int dq = t - 128;
        float4 e0 = mx[128 + dq], e1 = mx[192 + dq], e2 = mx[256 + dq], e3 = mx[320 + dq];
        float4 k4 = ((const float4*)(ka + (size_t)n * DDIM))[dq];
        out.x = g[0]*e0.x + g[1]*e1.x + g[2]*e2.x + g[3]*e3.x + g[4]*k4.x;
        out.y = g[0]*e0.y + g[1]*e1.y + g[2]*e2.y + g[3]*e3.y + g[4]*k4.y;
        out.z = g[0]*e0.z + g[1]*e1.z + g[2]*e2.z + g[3]*e3.z + g[4]*k4.z;
        out.w = g[0]*e0.w + g[1]*e1.w + g[2]*e2.w + g[3]*e3.w + g[4]*k4.w;
    } else {
        out = ((const float4*)(lf + (size_t)n * DLF))[t - 192];
    }
    const size_t e = (size_t)n * DSUM + t * 4;
    split_store(out.x, cth + e + 0, ctl + e + 0);
    split_store(out.y, cth + e + 1, ctl + e + 1);
    split_store(out.z, cth + e + 2, ctl + e + 2);
    split_store(out.w, cth + e + 3, ctl + e + 3);
}

// ---------------------------------------------------------------------------
// combine: cw = softmax(h @ W2 + b2); comb = cw*(cth+ctl) + resid (bf16 out)
// ---------------------------------------------------------------------------
__global__ void combine_kernel(const float* __restrict__ h, const float* __restrict__ W2,
                               const float* __restrict__ b2,
                               const __nv_bfloat16* __restrict__ cth,
                               const __nv_bfloat16* __restrict__ ctl,
                               const float* __restrict__ resid,
                               __nv_bfloat16* __restrict__ cbh, __nv_bfloat16* __restrict__ cbl)
{
    __shared__ float w2s[256];
    const int tid = threadIdx.x;
    w2s[tid] = W2[tid];
    __syncthreads();

    const int warp = tid >> 5, lane = tid & 31;
    const int n = (blockIdx.x << 3) + warp;

    float2 hv = *(const float2*)(h + (size_t)n * HIDD + lane * 2);
    const int a0 = lane * 2, a1 = lane * 2 + 1;
    float l0 = hv.x * w2s[a0*4+0] + hv.y * w2s[a1*4+0];
    float l1 = hv.x * w2s[a0*4+1] + hv.y * w2s[a1*4+1];
    float l2 = hv.x * w2s[a0*4+2] + hv.y * w2s[a1*4+2];
    float l3 = hv.x * w2s[a0*4+3] + hv.y * w2s[a1*4+3];
#pragma unroll
    for (int off = 16; off; off >>= 1) {
        l0 += __shfl_xor_sync(0xffffffffu, l0, off);
        l1 += __shfl_xor_sync(0xffffffffu, l1, off);
        l2 += __shfl_xor_sync(0xffffffffu, l2, off);
        l3 += __shfl_xor_sync(0xffffffffu, l3, off);
    }
    l0 += __ldg(b2 + 0); l1 += __ldg(b2 + 1); l2 += __ldg(b2 + 2); l3 += __ldg(b2 + 3);
    float mx = fmaxf(fmaxf(l0, l1), fmaxf(l2, l3));
    float e0 = __expf(l0 - mx), e1 = __expf(l1 - mx), e2 = __expf(l2 - mx), e3 = __expf(l3 - mx);
    float inv = 1.0f / (e0 + e1 + e2 + e3);
    float cw0 = e0 * inv, cw1 = e1 * inv, cw2 = e2 * inv, cw3 = e3 * inv;

    const __nv_bfloat162* ch = (const __nv_bfloat162*)(cth + (size_t)n * DSUM);
    const __nv_bfloat162* cl = (const __nv_bfloat162*)(ctl + (size_t)n * DSUM);
    const float4* rr = (const float4*)(resid + (size_t)n * DSUM);
#pragma unroll
    for (int q = 0; q < 12; q++) {
        int c4 = lane + (q << 5);
        float w = (c4 < 64) ? cw0 : (c4 < 128) ? cw1 : (c4 < 192) ? cw2 : cw3;
        __nv_bfloat162 h01 = ch[2 * c4], h23 = ch[2 * c4 + 1];
        __nv_bfloat162 l01 = cl[2 * c4], l23 = cl[2 * c4 + 1];
        float cx = __bfloat162float(h01.x) + __bfloat162float(l01.x);
        float cy = __bfloat162float(h01.y) + __bfloat162float(l01.y);
        float cz = __bfloat162float(h23.x) + __bfloat162float(l23.x);
        float cw_ = __bfloat162float(h23.y) + __bfloat162float(l23.y);
        float4 rv = rr[c4];
        float v0 = fmaf(w, cx, rv.x), v1 = fmaf(w, cy, rv.y);
        float v2 = fmaf(w, cz, rv.z), v3 = fmaf(w, cw_, rv.w);
        const size_t e = (size_t)n * DSUM + c4 * 4;
        split_store(v0, cbh + e + 0, cbl + e + 0);
        split_store(v1, cbh + e + 1, cbl + e + 1);
        split_store(v2, cbh + e + 2, cbl + e + 2);
        split_store(v3, cbh + e + 3, cbl + e + 3);
    }
}

// ---------------------------------------------------------------------------
// Host launcher
// ---------------------------------------------------------------------------
extern "C" void kernel_launch(void* const* d_in, const int* in_sizes, int n_in,
                              void* d_out, int out_size)
{
    (void)in_sizes; (void)n_in; (void)out_size;

    const float* x      = (const float*)d_in[0];
    const float* lf     = (const float*)d_in[1];
    const float* W_feat = (const float*)d_in[2];
    const float* b_feat = (const float*)d_in[3];
    const float* Wt     = (const float*)d_in[4];
    const float* bt     = (const float*)d_in[5];
    const float* Wt_a   = (const float*)d_in[6];
    const float* bt_a   = (const float*)d_in[7];
    const float* Wc     = (const float*)d_in[8];
    const float* bc     = (const float*)d_in[9];
    const float* Wc_a   = (const float*)d_in[10];
    const float* bc_a   = (const float*)d_in[11];
    const float* We     = (const float*)d_in[12];
    const float* be     = (const float*)d_in[13];
    const float* We_a   = (const float*)d_in[14];
    const float* be_a   = (const float*)d_in[15];
    const float* Wg     = (const float*)d_in[16];
    const float* bg     = (const float*)d_in[17];
    const float* Wphi   = (const float*)d_in[18];
    const float* bphi   = (const float*)d_in[19];
    const float* Wpsi1  = (const float*)d_in[20];
    const float* bpsi1  = (const float*)d_in[21];
    const float* Wpsi2  = (const float*)d_in[22];
    const float* bpsi2  = (const float*)d_in[23];
    const float* Wres   = (const float*)d_in[24];
    const float* bres   = (const float*)d_in[25];
    const float* W1     = (const float*)d_in[26];
    const float* b1     = (const float*)d_in[27];
    const float* W2     = (const float*)d_in[28];
    const float* b2     = (const float*)d_in[29];
    const float* Wo     = (const float*)d_in[30];
    const float* bo     = (const float*)d_in[31];
    float* out = (float*)d_out;

    float* s = nullptr;
    cudaGetSymbolAddress((void**)&s, g_scratch);
    float* adapt  = s + OFF_ADAPT;
    float* am     = s + OFF_AM;
    float* part   = s + OFF_PART;
    float* gate   = s + OFF_GATE;
    float* Wdyn   = s + OFF_WDYN;
    float* bcat   = s + OFF_BCAT;
    float* mix    = s + OFF_MIX;
    float* ka     = s + OFF_KA;
    float* resid  = s + OFF_RESID;
    float* hbuf   = s + OFF_H;
    float* kapart = s + OFF_KAPART;

    __nv_bfloat16* bb = (__nv_bfloat16*)(s + OFF_BF16);
    __nv_bfloat16 *xh = bb + BF_XH,   *xl = bb + BF_XL;
    __nv_bfloat16 *wfh = bb + BF_WFH, *wfl = bb + BF_WFL;
    __nv_bfloat16 *wdh = bb + BF_WDH, *wdl = bb + BF_WDL;
    __nv_bfloat16 *tph = bb + BF_TPH, *tpl = bb + BF_TPL;
    __nv_bfloat16 *wph = bb + BF_WPH, *wpl = bb + BF_WPL;
    __nv_bfloat16 *cth = bb + BF_CATH, *ctl = bb + BF_CATL;
    __nv_bfloat16 *wrh = bb + BF_WRH, *wrl = bb + BF_WRL;
    __nv_bfloat16 *w1h = bb + BF_W1H, *w1l = bb + BF_W1L;
    __nv_bfloat16 *cbh = bb + BF_CBH, *cbl = bb + BF_CBL;
    __nv_bfloat16 *woh = bb + BF_WOH, *wol = bb + BF_WOL;
    __nv_bfloat16 *wp1h = bb + BF_WP1H, *wp1l = bb + BF_WP1L;

    const int SM_FUSED = 100352;                       // fused_mix_ka
    const int SM_3C    = 3 * 65536 + 1024;             // 197632 fused_resid_h
    const int SM_3C64  = 3 * 32768 + 1024;             // 99328 small 3c GEMMs
    cudaFuncSetAttribute(gemm3c_hmma<false>, cudaFuncAttributeMaxDynamicSharedMemorySize, SM_3C64);
    cudaFuncSetAttribute(fused_mix_ka,  cudaFuncAttributeMaxDynamicSharedMemorySize, SM_FUSED);
    cudaFuncSetAttribute(fused_resid_h, cudaFuncAttributeMaxDynamicSharedMemorySize, SM_3C);

    // 1. x split
    split_kernel<<<1024, 256>>>(x, xh, xl);
    // 2. W_feat + Wpsi2 tsplit + bcat
    prep2_kernel<<<54, 256>>>(W_feat, wfh, wfl, Wpsi2, wph, wpl, bt, bc, be, bcat);
    // 3. Wres + W1 + Wo + Wpsi1^T tsplit
    prep3_kernel<<<3808, 256>>>(Wres, wrh, wrl, W1, w1h, w1l, Wo, woh, wol,
                                Wpsi1, wp1h, wp1l);
    // 4. adapt GEMM (3-combo)  [4096,128]   <-- ncu window
    gemm3c_hmma<false><<<dim3(2, 64), 256, SM_3C64>>>(xh, xl, wfh, wfl, b_feat, adapt, NTOK, ADIM, DDIM);
    // 5-6. am
    colsum_part_kernel<<<32, 128>>>(adapt, part);
    colsum_fin_kernel<<<1, 128>>>(part, am);
    // 7-8. dynamic weights + transpose-split
    dynw_kernel<<<384, 256>>>(Wt, Wt_a, bt_a, Wc, Wc_a, bc_a, We, We_a, be_a, am, Wdyn);
    tsplit_kernel<<<384, 256>>>(Wdyn, wdh, wdl, DDIM, DSUM);
    // 9. gate softmax
    gate_kernel<<<NTOK / 8, 256>>>(adapt, Wg, bg, gate);
    // 10. FUSED: mix GEMM (384) + KA stage 1 HMMA (256)
    fused_mix_ka<<<640, 256, SM_FUSED>>>(xh, xl, wdh, wdl, bcat, mix,
                                         x, Wphi, bphi, wp1h, wp1l, kapart);
    // 11. KA finish
    ka_finish_kernel<<<256, 256>>>(kapart, bpsi1, tph, tpl);
    // 12. ka = tpsi @ Wpsi2 + bpsi2 (3-combo, K=64: single stage)  [4096,256]
    gemm3c_hmma<false><<<dim3(4, 64), 256, SM_3C64>>>(tph, tpl, wph, wpl, bpsi2, ka, NTOK, DDIM, HIDD);
    // 13. concat (bf16 hi/lo only)
    concat_kernel<<<NTOK, 384>>>(mix, gate, ka, lf, cth, ctl);
    // 14. FUSED: resid GEMM 3-combo 3-stage (384) + h GEMM 3-combo (64)
    fused_resid_h<<<448, 256, SM_3C>>>(cth, ctl, wrh, wrl, bres, resid,
                                       w1h, w1l, b1, hbuf);
    // 15. combine (reads bf16 concat, emits bf16 hi/lo)
    combine_kernel<<<NTOK / 8, 256>>>(hbuf, W2, b2, cth, ctl, resid, cbh, cbl);
    // 16. out = comb @ Wo + bo (3-combo)  [4096,256]
    gemm3c_hmma<false><<<dim3(4, 64), 256, SM_3C64>>>(cbh, cbl, woh, wol, bo, out, NTOK, DDIM, DSUM);
}